// round 10
// baseline (speedup 1.0000x reference)
#include <cuda_runtime.h>
#include <cuda_fp16.h>

typedef unsigned long long ull;
typedef unsigned int uint;

#define Bsz 1024
#define Tsz 512
#define Isz 128
#define Hsz 256
#define Osz 64
#define NB  16
#define NCTA 64
#define STHR 512
#define XSTR 136    // gemm smem row stride (halves)
#define HSTR 264    // scan h16/v16 row stride (halves): conflict-free ldmatrix

// ---------------- device scratch -----------------------------------------------------
__device__ __half g_xi[(size_t)Tsz * Bsz * 1024];    // 1.07 GB
__device__ __half g_wh[(size_t)1024 * Isz];          // [W_ih;Wt] fp16 for prepass
__device__ uint2  g_Whf[96 * 16 * 32];               // W_hh fragment-major fp16 (393 KB)
__device__ uint2  g_Wof[16 * 16 * 32];               // [Wo;Wg] fragment-major fp16 (64 KB)

// ---------------- helpers --------------------------------------------------------------
__device__ __forceinline__ float sigmf(float x) { return 1.0f / (1.0f + __expf(-x)); }
__device__ __forceinline__ float tanhf_(float x) {
    float a = fabsf(x);
    float e = __expf(-2.0f * a);
    return copysignf((1.0f - e) / (1.0f + e), x);
}
__device__ __forceinline__ uint smem_u32(const void* p) {
    uint a;
    asm("{ .reg .u64 t; cvta.to.shared.u64 t, %1; cvt.u32.u64 %0, t; }" : "=r"(a) : "l"(p));
    return a;
}
__device__ __forceinline__ void ldm_x4(uint* a, const __half* p) {
    uint addr = smem_u32(p);
    asm volatile("ldmatrix.sync.aligned.m8n8.x4.shared.b16 {%0,%1,%2,%3}, [%4];"
                 : "=r"(a[0]), "=r"(a[1]), "=r"(a[2]), "=r"(a[3]) : "r"(addr));
}
__device__ __forceinline__ void ldm_x2(uint* b, const __half* p) {
    uint addr = smem_u32(p);
    asm volatile("ldmatrix.sync.aligned.m8n8.x2.shared.b16 {%0,%1}, [%2];"
                 : "=r"(b[0]), "=r"(b[1]) : "r"(addr));
}
__device__ __forceinline__ void mma16816(float* d, const uint* a, const uint* b) {
    asm volatile(
        "mma.sync.aligned.m16n8k16.row.col.f32.f16.f16.f32 "
        "{%0,%1,%2,%3}, {%4,%5,%6,%7}, {%8,%9}, {%0,%1,%2,%3};"
        : "+f"(d[0]), "+f"(d[1]), "+f"(d[2]), "+f"(d[3])
        : "r"(a[0]), "r"(a[1]), "r"(a[2]), "r"(a[3]), "r"(b[0]), "r"(b[1]));
}

// ---------------- packing kernels -------------------------------------------------------
__global__ void pack_wh(const float* __restrict__ Wih, const float* __restrict__ Wt) {
    int i = blockIdx.x * blockDim.x + threadIdx.x;
    if (i >= (1024 * Isz) / 8) return;
    int row = i >> 4, q = i & 15;
    const float* s = (row < 768) ? (Wih + (size_t)row * Isz + q * 8)
                                 : (Wt + (size_t)(row - 768) * Isz + q * 8);
    float4 f0 = __ldg((const float4*)s), f1 = __ldg((const float4*)s + 1);
    __half2 h0 = __floats2half2_rn(f0.x, f0.y), h1 = __floats2half2_rn(f0.z, f0.w);
    __half2 h2 = __floats2half2_rn(f1.x, f1.y), h3 = __floats2half2_rn(f1.z, f1.w);
    *(uint4*)(g_wh + (size_t)i * 8) =
        make_uint4(*(uint*)&h0, *(uint*)&h1, *(uint*)&h2, *(uint*)&h3);
}
// Fragment packing for m16n8k16 .col B operand.
__global__ void prep_whhf(const float* __restrict__ Whh) {
    int idx = blockIdx.x * blockDim.x + threadIdx.x;
    if (idx >= 96 * 16 * 32) return;
    int lane = idx & 31, kt = (idx >> 5) & 15, nt = idx >> 9;
    int n = nt * 8 + (lane >> 2);
    int k0 = kt * 16 + (lane & 3) * 2;
    const float* s = Whh + (size_t)n * Hsz;
    __half2 lo = __floats2half2_rn(s[k0], s[k0 + 1]);
    __half2 hi = __floats2half2_rn(s[k0 + 8], s[k0 + 9]);
    g_Whf[idx] = make_uint2(*(uint*)&lo, *(uint*)&hi);
}
__global__ void prep_wof(const float* __restrict__ Wo, const float* __restrict__ Wg) {
    int idx = blockIdx.x * blockDim.x + threadIdx.x;
    if (idx >= 16 * 16 * 32) return;
    int lane = idx & 31, kt = (idx >> 5) & 15, nt = idx >> 9;
    int n = nt * 8 + (lane >> 2);
    int k0 = kt * 16 + (lane & 3) * 2;
    const float* s = (n < 64) ? (Wo + (size_t)n * Hsz) : (Wg + (size_t)(n - 64) * Hsz);
    __half2 lo = __floats2half2_rn(s[k0], s[k0 + 1]);
    __half2 hi = __floats2half2_rn(s[k0 + 8], s[k0 + 9]);
    g_Wof[idx] = make_uint2(*(uint*)&lo, *(uint*)&hi);
}

// ---------------- HMMA prepass GEMM v2: warp tile 64x32, 2 CTAs/SM ---------------------
__global__ void __launch_bounds__(256, 2) gemm_xi(const float* __restrict__ x,
                                                  const float* __restrict__ b_ih,
                                                  const float* __restrict__ bt) {
    extern __shared__ __align__(16) __half sh[];
    __half* Xs = sh;                  // [128][XSTR]
    __half* Ws = sh + 128 * XSTR;     // [128][XSTR]

    const int tid = threadIdx.x, wid = tid >> 5, lane = tid & 31;
    const int rbase0 = blockIdx.x * 128;
    const int wm = wid & 1, wn = wid >> 1;   // 2x4: 64 rows x 32 cols per warp

    { // stage X tile, fp32 -> fp16 fused
#pragma unroll
        for (int i = tid; i < 2048; i += 256) {
            int row = i >> 4, q = i & 15;
            const float4* s = (const float4*)(x + (size_t)(rbase0 + row) * Isz + q * 8);
            float4 f0 = __ldg(s), f1 = __ldg(s + 1);
            __half2 h0 = __floats2half2_rn(f0.x, f0.y), h1 = __floats2half2_rn(f0.z, f0.w);
            __half2 h2 = __floats2half2_rn(f1.x, f1.y), h3 = __floats2half2_rn(f1.z, f1.w);
            *(uint4*)(Xs + row * XSTR + q * 8) =
                make_uint4(*(uint*)&h0, *(uint*)&h1, *(uint*)&h2, *(uint*)&h3);
        }
    }

    for (int chunk = 0; chunk < 8; ++chunk) {    // 128 output cols per chunk
        {
            const uint4* src = (const uint4*)(g_wh + (size_t)chunk * 128 * Isz);
#pragma unroll
            for (int i = tid; i < 2048; i += 256) {
                int row = i >> 4, q = i & 15;
                *(uint4*)(Ws + row * XSTR + q * 8) = __ldg(src + row * 16 + q);
            }
        }
        __syncthreads();

        float acc[4][4][4];
#pragma unroll
        for (int mf = 0; mf < 4; ++mf)
#pragma unroll
            for (int nf = 0; nf < 4; ++nf)
#pragma unroll
                for (int q = 0; q < 4; ++q) acc[mf][nf][q] = 0.0f;

#pragma unroll
        for (int k = 0; k < 8; ++k) {
            uint a[4][4];
#pragma unroll
            for (int mf = 0; mf < 4; ++mf)
                ldm_x4(a[mf], Xs + (wm * 64 + mf * 16 + (lane & 15)) * XSTR
                                 + k * 16 + (lane >> 4) * 8);
            uint bf[4][2];
#pragma unroll
            for (int nf = 0; nf < 4; ++nf)
                ldm_x2(bf[nf], Ws + (wn * 32 + nf * 8 + (lane & 7)) * XSTR
                                  + k * 16 + ((lane >> 3) & 1) * 8);
#pragma unroll
            for (int mf = 0; mf < 4; ++mf)
#pragma unroll
                for (int nf = 0; nf < 4; ++nf)
                    mma16816(acc[mf][nf], a[mf], bf[nf]);
        }

        const bool do_silu = (chunk >= 6);
#pragma unroll
        for (int nf = 0; nf < 4; ++nf) {
            int c = chunk * 128 + wn * 32 + nf * 8 + (lane & 3) * 2;
            float bias0, bias1;
            if (!do_silu) { bias0 = __ldg(b_ih + c); bias1 = __ldg(b_ih + c + 1); }
            else          { bias0 = __ldg(bt + c - 768); bias1 = __ldg(bt + c - 767); }
#pragma unroll
            for (int mf = 0; mf < 4; ++mf) {
                int r1 = rbase0 + wm * 64 + mf * 16 + (lane >> 2);
#pragma unroll
                for (int h = 0; h < 2; ++h) {
                    int rr = r1 + h * 8;
                    float v0 = acc[mf][nf][2 * h]     + bias0;
                    float v1 = acc[mf][nf][2 * h + 1] + bias1;
                    if (do_silu) { v0 *= sigmf(v0); v1 *= sigmf(v1); }
                    int b = rr >> 9, t = rr & 511;
                    *(__half2*)(g_xi + ((size_t)t * Bsz + b) * 1024 + c) =
                        __floats2half2_rn(v0, v1);
                }
            }
        }
        __syncthreads();
    }
}

// ---------------- persistent GRU scan: 16 batches/CTA, 64 CTAs --------------------------
// smem map (bytes):
//   h32  [16][256] f32   @ 0       (16384)
//   hh   [16][776] f32   @ 16384   (49664)
//   h16  [16][HSTR] f16  @ 66048   (8448)
//   v16  [16][HSTR] f16  @ 74496   (8448)
//   xi   [16][1024] f16  @ 82944   (32768)
//   redD [16][128] f32   @ 115712  (8192)   -> total 123904
__global__ void __launch_bounds__(STHR, 1) gru_scan(
    const float* __restrict__ h0, const float* __restrict__ b_hh,
    const float* __restrict__ bo, const float* __restrict__ bg,
    float* __restrict__ out)
{
    extern __shared__ __align__(16) char smraw[];
    float*  h32  = (float*)smraw;
    float*  hh   = (float*)(smraw + 16384);
    __half* h16  = (__half*)(smraw + 66048);
    __half* v16  = (__half*)(smraw + 74496);
    __half* xi_s = (__half*)(smraw + 82944);
    float*  redD = (float*)(smraw + 115712);

    const int tid  = threadIdx.x;
    const int w    = tid >> 5, lane = tid & 31;
    const int j    = tid & 255;       // hidden unit (phase C)
    const int kh   = tid >> 8;        // batch-half for phase C
    const int b0   = blockIdx.x * NB;

    // ldmatrix A addressing: 16 real batch rows
    const __half* aB_base = h16 + (lane & 15) * HSTR + (lane >> 4) * 8;
    const int bat = lane >> 2, c0 = 2 * (lane & 3);

    { // init h32 + h16 from h0: thread covers (b = tid>>5, 8 cols)
        int b = tid >> 5, k0 = (tid & 31) * 8;
        const float4* p = (const float4*)(h0 + (size_t)(b0 + b) * Hsz + k0);
        float4 v0 = p[0], v1 = p[1];
        *(float4*)&h32[b * 256 + k0]     = v0;
        *(float4*)&h32[b * 256 + k0 + 4] = v1;
        __half2 a0 = __floats2half2_rn(v0.x, v0.y), a1 = __floats2half2_rn(v0.z, v0.w);
        __half2 a2 = __floats2half2_rn(v1.x, v1.y), a3 = __floats2half2_rn(v1.z, v1.w);
        *(uint4*)&h16[b * HSTR + k0] =
            make_uint4(*(uint*)&a0, *(uint*)&a1, *(uint*)&a2, *(uint*)&a3);
    }

    const float hbr = b_hh[j], hbz = b_hh[Hsz + j], hbn = b_hh[2 * Hsz + j];
    float boT = 0.f, bgT = 0.f;
    if (tid < 64) { boT = bo[tid]; bgT = bg[tid]; }
    float oacc[NB];
#pragma unroll
    for (int b = 0; b < NB; ++b) oacc[b] = 0.0f;
    __syncthreads();

    for (int t = 0; t < Tsz; ++t) {
        { // stage xi slice: 16 batches x 1024 halves = 32 KB
            const uint4* src = (const uint4*)(g_xi + ((size_t)t * Bsz + b0) * 1024);
            uint4* dst = (uint4*)xi_s;
#pragma unroll
            for (int i = 0; i < 4; ++i)
                dst[tid + 512 * i] = __ldg(src + tid + 512 * i);
        }

        // ---- Phase B: hh = h @ W_hh^T via HMMA (M=16 real batches) ----
        {
            float acc[6][4];
#pragma unroll
            for (int i = 0; i < 6; ++i)
#pragma unroll
                for (int q = 0; q < 4; ++q) acc[i][q] = 0.0f;
#pragma unroll
            for (int kt = 0; kt < 16; ++kt) {
                uint a[4];
                ldm_x4(a, aB_base + kt * 16);
#pragma unroll
                for (int i = 0; i < 6; ++i) {
                    const int nt = w + 16 * i;
                    uint2 wf = __ldg(&g_Whf[(nt * 16 + kt) * 32 + lane]);
                    mma16816(acc[i], a, (uint*)&wf);
                }
            }
#pragma unroll
            for (int i = 0; i < 6; ++i) {
                const int nt = w + 16 * i;
                *(float2*)&hh[bat * 776 + nt * 8 + c0] =
                    make_float2(acc[i][0], acc[i][1]);
                *(float2*)&hh[(bat + 8) * 776 + nt * 8 + c0] =
                    make_float2(acc[i][2], acc[i][3]);
            }
        }
        __syncthreads();  // bar1: hh ready, xi staged, h16 reads done

        // ---- Phase C: gates + state update; thread (kh,j) does 8 batches ----
#pragma unroll
        for (int i = 0; i < 8; ++i) {
            const int bb = 8 * kh + i;
            const __half* xp = xi_s + bb * 1024 + j;
            float xr = __half2float(xp[0]);
            float xz = __half2float(xp[256]);
            float xn = __half2float(xp[512]);
            float xt = __half2float(xp[768]);
            const float* hhb = hh + bb * 776;
            float r  = sigmf(xr + hhb[j] + hbr);
            float z  = sigmf(xz + hhb[256 + j] + hbz);
            float n  = tanhf_(xn + r * (hhb[512 + j] + hbn));
            float hp = h32[bb * 256 + j];
            float hnew = n + z * (hp - n);
            float vv = hnew + xt;            // ti pre-silu'd
            h32[bb * 256 + j] = hnew;
            h16[bb * HSTR + j] = __float2half_rn(hnew);
            v16[bb * HSTR + j] = __float2half_rn(vv);
        }
        __syncthreads();  // bar2: new h16/v16/h32 visible

        // ---- Phase D: proj/gate via HMMA; warp w = n-tile w (0-7 Wo/v, 8-15 Wg/h) ----
        {
            const __half* aD = ((w < 8) ? v16 : h16) + (lane & 15) * HSTR
                               + (lane >> 4) * 8;
            float acc[4] = {0.f, 0.f, 0.f, 0.f};
#pragma unroll
            for (int kt = 0; kt < 16; ++kt) {
                uint a[4];
                ldm_x4(a, aD + kt * 16);
                uint2 wf = __ldg(&g_Wof[(w * 16 + kt) * 32 + lane]);
                mma16816(acc, a, (uint*)&wf);
            }
            *(float2*)&redD[bat * 128 + w * 8 + c0] = make_float2(acc[0], acc[1]);
            *(float2*)&redD[(bat + 8) * 128 + w * 8 + c0] = make_float2(acc[2], acc[3]);
        }
        __syncthreads();  // bar3: redD ready

        if (tid < 64) {
#pragma unroll
            for (int b = 0; b < NB; ++b) {
                float pr = redD[b * 128 + tid] + boT;
                float gt = redD[b * 128 + 64 + tid] + bgT;
                oacc[b] += pr * sigmf(gt);
            }
        }
    }

    if (tid < 64) {
        const float inv = 1.0f / (float)Tsz;
#pragma unroll
        for (int b = 0; b < NB; ++b)
            out[(size_t)(b0 + b) * Osz + tid] = oacc[b] * inv;
    }
}

// ---------------- launch -----------------------------------------------------------------
extern "C" void kernel_launch(void* const* d_in, const int* in_sizes, int n_in,
                              void* d_out, int out_size) {
    const float* x    = (const float*)d_in[0];
    const float* h0   = (const float*)d_in[1];
    const float* W_ih = (const float*)d_in[2];
    const float* b_ih = (const float*)d_in[3];
    const float* W_hh = (const float*)d_in[4];
    const float* b_hh = (const float*)d_in[5];
    const float* Wt   = (const float*)d_in[6];
    const float* bt   = (const float*)d_in[7];
    const float* Wo   = (const float*)d_in[8];
    const float* bo   = (const float*)d_in[9];
    const float* Wg   = (const float*)d_in[10];
    const float* bg   = (const float*)d_in[11];
    float* out = (float*)d_out;

    const int GEMM_SMEM = (128 + 128) * XSTR * 2;   // 69632
    const int SCAN_SMEM = 123904;
    cudaFuncSetAttribute(gemm_xi, cudaFuncAttributeMaxDynamicSharedMemorySize, GEMM_SMEM);
    cudaFuncSetAttribute(gru_scan, cudaFuncAttributeMaxDynamicSharedMemorySize, SCAN_SMEM);

    pack_wh<<<(1024 * Isz / 8 + 255) / 256, 256>>>(W_ih, Wt);
    prep_whhf<<<(96 * 16 * 32 + 255) / 256, 256>>>(W_hh);
    prep_wof<<<(16 * 16 * 32 + 255) / 256, 256>>>(Wo, Wg);
    gemm_xi<<<(Bsz * Tsz) / 128, 256, GEMM_SMEM>>>(x, b_ih, bt);
    gru_scan<<<NCTA, STHR, SCAN_SMEM>>>(h0, b_hh, bo, bg, out);
}

// round 11
// speedup vs baseline: 1.2660x; 1.2660x over previous
#include <cuda_runtime.h>
#include <cuda_fp16.h>

typedef unsigned long long ull;
typedef unsigned int uint;

#define Bsz 1024
#define Tsz 512
#define Isz 128
#define Hsz 256
#define Osz 64
#define NB  8
#define NCTA 128
#define STHR 512
#define XSTR 136    // gemm smem row stride (halves)
#define HSTR 264    // scan h16/v16 row stride (halves): conflict-free ldmatrix
#define NTC 40      // W_hh fragment n-tiles cached in smem (of 96)

// ---------------- device scratch -----------------------------------------------------
// g_xi layout [b][t][1024]: 0..255 xr, 256..511 xz, 512..767 xn (+b_ih), 768..1023 silu
__device__ __half g_xi[(size_t)Bsz * Tsz * 1024];    // 1.07 GB
__device__ __half g_wh[(size_t)1024 * Isz];          // [W_ih;Wt] fp16 for prepass
__device__ uint2  g_Whf[96 * 16 * 32];               // W_hh fragment-major fp16 (393 KB)
__device__ uint2  g_Wof[16 * 16 * 32];               // [Wo;Wg] fragment-major fp16 (64 KB)

// ---------------- helpers --------------------------------------------------------------
__device__ __forceinline__ float sigmf(float x) { return 1.0f / (1.0f + __expf(-x)); }
__device__ __forceinline__ float tanhf_(float x) {
    float a = fabsf(x);
    float e = __expf(-2.0f * a);
    return copysignf((1.0f - e) / (1.0f + e), x);
}
__device__ __forceinline__ uint smem_u32(const void* p) {
    uint a;
    asm("{ .reg .u64 t; cvta.to.shared.u64 t, %1; cvt.u32.u64 %0, t; }" : "=r"(a) : "l"(p));
    return a;
}
__device__ __forceinline__ void ldm_x4(uint* a, const __half* p) {
    uint addr = smem_u32(p);
    asm volatile("ldmatrix.sync.aligned.m8n8.x4.shared.b16 {%0,%1,%2,%3}, [%4];"
                 : "=r"(a[0]), "=r"(a[1]), "=r"(a[2]), "=r"(a[3]) : "r"(addr));
}
__device__ __forceinline__ void ldm_x2(uint* b, const __half* p) {
    uint addr = smem_u32(p);
    asm volatile("ldmatrix.sync.aligned.m8n8.x2.shared.b16 {%0,%1}, [%2];"
                 : "=r"(b[0]), "=r"(b[1]) : "r"(addr));
}
__device__ __forceinline__ void mma16816(float* d, const uint* a, const uint* b) {
    asm volatile(
        "mma.sync.aligned.m16n8k16.row.col.f32.f16.f16.f32 "
        "{%0,%1,%2,%3}, {%4,%5,%6,%7}, {%8,%9}, {%0,%1,%2,%3};"
        : "+f"(d[0]), "+f"(d[1]), "+f"(d[2]), "+f"(d[3])
        : "r"(a[0]), "r"(a[1]), "r"(a[2]), "r"(a[3]), "r"(b[0]), "r"(b[1]));
}

// ---------------- packing kernels -------------------------------------------------------
__global__ void pack_wh(const float* __restrict__ Wih, const float* __restrict__ Wt) {
    int i = blockIdx.x * blockDim.x + threadIdx.x;
    if (i >= (1024 * Isz) / 8) return;
    int row = i >> 4, q = i & 15;
    const float* s = (row < 768) ? (Wih + (size_t)row * Isz + q * 8)
                                 : (Wt + (size_t)(row - 768) * Isz + q * 8);
    float4 f0 = __ldg((const float4*)s), f1 = __ldg((const float4*)s + 1);
    __half2 h0 = __floats2half2_rn(f0.x, f0.y), h1 = __floats2half2_rn(f0.z, f0.w);
    __half2 h2 = __floats2half2_rn(f1.x, f1.y), h3 = __floats2half2_rn(f1.z, f1.w);
    *(uint4*)(g_wh + (size_t)i * 8) =
        make_uint4(*(uint*)&h0, *(uint*)&h1, *(uint*)&h2, *(uint*)&h3);
}
// Fragment packing for m16n8k16 .col B operand.
__global__ void prep_whhf(const float* __restrict__ Whh) {
    int idx = blockIdx.x * blockDim.x + threadIdx.x;
    if (idx >= 96 * 16 * 32) return;
    int lane = idx & 31, kt = (idx >> 5) & 15, nt = idx >> 9;
    int n = nt * 8 + (lane >> 2);
    int k0 = kt * 16 + (lane & 3) * 2;
    const float* s = Whh + (size_t)n * Hsz;
    __half2 lo = __floats2half2_rn(s[k0], s[k0 + 1]);
    __half2 hi = __floats2half2_rn(s[k0 + 8], s[k0 + 9]);
    g_Whf[idx] = make_uint2(*(uint*)&lo, *(uint*)&hi);
}
__global__ void prep_wof(const float* __restrict__ Wo, const float* __restrict__ Wg) {
    int idx = blockIdx.x * blockDim.x + threadIdx.x;
    if (idx >= 16 * 16 * 32) return;
    int lane = idx & 31, kt = (idx >> 5) & 15, nt = idx >> 9;
    int n = nt * 8 + (lane >> 2);
    int k0 = kt * 16 + (lane & 3) * 2;
    const float* s = (n < 64) ? (Wo + (size_t)n * Hsz) : (Wg + (size_t)(n - 64) * Hsz);
    __half2 lo = __floats2half2_rn(s[k0], s[k0 + 1]);
    __half2 hi = __floats2half2_rn(s[k0 + 8], s[k0 + 9]);
    g_Wof[idx] = make_uint2(*(uint*)&lo, *(uint*)&hi);
}

// ---------------- HMMA prepass GEMM: xi = X @ W^T (+bias, +silu cols>=768) -------------
// g_xi rows are rr = b*Tsz + t (same order as x rows) -> coalesced epilogue stores.
__global__ void __launch_bounds__(256, 2) gemm_xi(const float* __restrict__ x,
                                                  const float* __restrict__ b_ih,
                                                  const float* __restrict__ bt) {
    extern __shared__ __align__(16) __half sh[];
    __half* Xs = sh;                  // [128][XSTR]
    __half* Ws = sh + 128 * XSTR;     // [128][XSTR]

    const int tid = threadIdx.x, wid = tid >> 5, lane = tid & 31;
    const int rbase0 = blockIdx.x * 128;
    const int wm = wid & 1, wn = wid >> 1;   // 2x4: 64 rows x 32 cols per warp

    { // stage X tile, fp32 -> fp16 fused
#pragma unroll
        for (int i = tid; i < 2048; i += 256) {
            int row = i >> 4, q = i & 15;
            const float4* s = (const float4*)(x + (size_t)(rbase0 + row) * Isz + q * 8);
            float4 f0 = __ldg(s), f1 = __ldg(s + 1);
            __half2 h0 = __floats2half2_rn(f0.x, f0.y), h1 = __floats2half2_rn(f0.z, f0.w);
            __half2 h2 = __floats2half2_rn(f1.x, f1.y), h3 = __floats2half2_rn(f1.z, f1.w);
            *(uint4*)(Xs + row * XSTR + q * 8) =
                make_uint4(*(uint*)&h0, *(uint*)&h1, *(uint*)&h2, *(uint*)&h3);
        }
    }

    for (int chunk = 0; chunk < 8; ++chunk) {    // 128 output cols per chunk
        {
            const uint4* src = (const uint4*)(g_wh + (size_t)chunk * 128 * Isz);
#pragma unroll
            for (int i = tid; i < 2048; i += 256) {
                int row = i >> 4, q = i & 15;
                *(uint4*)(Ws + row * XSTR + q * 8) = __ldg(src + row * 16 + q);
            }
        }
        __syncthreads();

        float acc[4][4][4];
#pragma unroll
        for (int mf = 0; mf < 4; ++mf)
#pragma unroll
            for (int nf = 0; nf < 4; ++nf)
#pragma unroll
                for (int q = 0; q < 4; ++q) acc[mf][nf][q] = 0.0f;

#pragma unroll
        for (int k = 0; k < 8; ++k) {
            uint a[4][4];
#pragma unroll
            for (int mf = 0; mf < 4; ++mf)
                ldm_x4(a[mf], Xs + (wm * 64 + mf * 16 + (lane & 15)) * XSTR
                                 + k * 16 + (lane >> 4) * 8);
            uint bf[4][2];
#pragma unroll
            for (int nf = 0; nf < 4; ++nf)
                ldm_x2(bf[nf], Ws + (wn * 32 + nf * 8 + (lane & 7)) * XSTR
                                  + k * 16 + ((lane >> 3) & 1) * 8);
#pragma unroll
            for (int mf = 0; mf < 4; ++mf)
#pragma unroll
                for (int nf = 0; nf < 4; ++nf)
                    mma16816(acc[mf][nf], a[mf], bf[nf]);
        }

        const bool do_silu = (chunk >= 6);
#pragma unroll
        for (int nf = 0; nf < 4; ++nf) {
            int c = chunk * 128 + wn * 32 + nf * 8 + (lane & 3) * 2;
            float bias0, bias1;
            if (!do_silu) { bias0 = __ldg(b_ih + c); bias1 = __ldg(b_ih + c + 1); }
            else          { bias0 = __ldg(bt + c - 768); bias1 = __ldg(bt + c - 767); }
#pragma unroll
            for (int mf = 0; mf < 4; ++mf) {
                int r1 = rbase0 + wm * 64 + mf * 16 + (lane >> 2);
#pragma unroll
                for (int h = 0; h < 2; ++h) {
                    int rr = r1 + h * 8;
                    float v0 = acc[mf][nf][2 * h]     + bias0;
                    float v1 = acc[mf][nf][2 * h + 1] + bias1;
                    if (do_silu) { v0 *= sigmf(v0); v1 *= sigmf(v1); }
                    *(__half2*)(g_xi + (size_t)rr * 1024 + c) = __floats2half2_rn(v0, v1);
                }
            }
        }
        __syncthreads();
    }
}

// ---------------- persistent GRU scan: NB=8, 128 CTAs, smem-cached fragments ------------
// smem map (bytes):
//   h32  [8][256] f32   @ 0      (8192)
//   hh   [8][776] f32   @ 8192   (24832)
//   h16  [8][HSTR] f16  @ 33024  (4224)
//   v16  [8][HSTR] f16  @ 37248  (4224)
//   xi   [8][1024] f16  @ 41472  (16384)
//   redD [8][128] f32   @ 57856  (4096)
//   whf  [NTC*16*32] u2 @ 61952  (163840)  -> total 225792
__global__ void __launch_bounds__(STHR, 1) gru_scan(
    const float* __restrict__ h0, const float* __restrict__ b_hh,
    const float* __restrict__ bo, const float* __restrict__ bg,
    float* __restrict__ out)
{
    extern __shared__ __align__(16) char smraw[];
    float*  h32   = (float*)smraw;
    float*  hh    = (float*)(smraw + 8192);
    __half* h16   = (__half*)(smraw + 33024);
    __half* v16   = (__half*)(smraw + 37248);
    __half* xi_s  = (__half*)(smraw + 41472);
    float*  redD  = (float*)(smraw + 57856);
    uint2*  whf_s = (uint2*)(smraw + 61952);

    const int tid  = threadIdx.x;
    const int w    = tid >> 5, lane = tid & 31;
    const int j    = tid & 255;       // hidden unit (phase C)
    const int kh   = tid >> 8;        // batch-half for phase C
    const int b0   = blockIdx.x * NB;

    const __half* aB_base = h16 + (lane & 7) * HSTR + ((lane >= 16) ? 8 : 0);
    const int bat = lane >> 2, c0 = 2 * (lane & 3);

    { // init h32 + h16 from h0
        int b = tid >> 6, k0 = (tid & 63) * 4;
        const float4 v = *(const float4*)(h0 + (size_t)(b0 + b) * Hsz + k0);
        *(float4*)&h32[b * 256 + k0] = v;
        __half2 a0 = __floats2half2_rn(v.x, v.y), a1 = __floats2half2_rn(v.z, v.w);
        *(uint2*)&h16[b * HSTR + k0] = make_uint2(*(uint*)&a0, *(uint*)&a1);
    }
    { // one-time: cache W_hh fragments for n-tiles [0, NTC)
        for (int i = tid; i < NTC * 16 * 32; i += STHR)
            whf_s[i] = __ldg(g_Whf + i);
    }

    const float hbr = b_hh[j], hbz = b_hh[Hsz + j], hbn = b_hh[2 * Hsz + j];
    float boT = 0.f, bgT = 0.f;
    if (tid < 64) { boT = bo[tid]; bgT = bg[tid]; }
    float oacc[NB];
#pragma unroll
    for (int b = 0; b < NB; ++b) oacc[b] = 0.0f;
    __syncthreads();

    for (int t = 0; t < Tsz; ++t) {
        { // stage xi slice: 8 batches x 2KB, [b][t] layout
#pragma unroll
            for (int ii = 0; ii < 2; ++ii) {
                int i = tid + 512 * ii;
                int b = i >> 7, q = i & 127;
                ((uint4*)xi_s)[i] = __ldg(
                    (const uint4*)(g_xi + ((size_t)(b0 + b) * Tsz + t) * 1024) + q);
            }
        }

        // ---- Phase B: hh = h @ W_hh^T via HMMA; fragments from smem when cached ----
        {
            float acc[6][4];
#pragma unroll
            for (int i = 0; i < 6; ++i)
#pragma unroll
                for (int q = 0; q < 4; ++q) acc[i][q] = 0.0f;
#pragma unroll
            for (int kt = 0; kt < 16; ++kt) {
                uint a[4];
                ldm_x4(a, aB_base + kt * 16);
#pragma unroll
                for (int i = 0; i < 6; ++i) {
                    const int nt = w + 16 * i;
                    uint2 wf = (nt < NTC)
                        ? whf_s[(nt * 16 + kt) * 32 + lane]
                        : __ldg(&g_Whf[(nt * 16 + kt) * 32 + lane]);
                    mma16816(acc[i], a, (uint*)&wf);
                }
            }
#pragma unroll
            for (int i = 0; i < 6; ++i) {
                const int nt = w + 16 * i;
                *(float2*)&hh[bat * 776 + nt * 8 + c0] = make_float2(acc[i][0], acc[i][1]);
            }
        }
        __syncthreads();  // bar1: hh ready, xi staged, h16 reads done

        // ---- Phase C: gates + state update; thread (kh,j) does 4 batches ----
#pragma unroll
        for (int i = 0; i < 4; ++i) {
            const int bb = 4 * kh + i;
            const __half* xp = xi_s + bb * 1024 + j;
            float xr = __half2float(xp[0]);
            float xz = __half2float(xp[256]);
            float xn = __half2float(xp[512]);
            float xt = __half2float(xp[768]);
            const float* hhb = hh + bb * 776;
            float r  = sigmf(xr + hhb[j] + hbr);
            float z  = sigmf(xz + hhb[256 + j] + hbz);
            float n  = tanhf_(xn + r * (hhb[512 + j] + hbn));
            float hp = h32[bb * 256 + j];
            float hnew = n + z * (hp - n);
            float vv = hnew + xt;            // ti pre-silu'd
            h32[bb * 256 + j] = hnew;
            h16[bb * HSTR + j] = __float2half_rn(hnew);
            v16[bb * HSTR + j] = __float2half_rn(vv);
        }
        __syncthreads();  // bar2: new h16/v16/h32 visible

        // ---- Phase D: proj/gate via HMMA; warp w (0-7: Wo/v, 8-15: Wg/h) ----
        {
            const __half* aD = ((w < 8) ? v16 : h16) + (lane & 7) * HSTR
                               + ((lane >= 16) ? 8 : 0);
            float acc[4] = {0.f, 0.f, 0.f, 0.f};
#pragma unroll
            for (int kt = 0; kt < 16; ++kt) {
                uint a[4];
                ldm_x4(a, aD + kt * 16);
                uint2 wf = __ldg(&g_Wof[(w * 16 + kt) * 32 + lane]);
                mma16816(acc, a, (uint*)&wf);
            }
            *(float2*)&redD[bat * 128 + w * 8 + c0] = make_float2(acc[0], acc[1]);
        }
        __syncthreads();  // bar3: redD ready

        if (tid < 64) {
#pragma unroll
            for (int b = 0; b < NB; ++b) {
                float pr = redD[b * 128 + tid] + boT;
                float gt = redD[b * 128 + 64 + tid] + bgT;
                oacc[b] += pr * sigmf(gt);
            }
        }
    }

    if (tid < 64) {
        const float inv = 1.0f / (float)Tsz;
#pragma unroll
        for (int b = 0; b < NB; ++b)
            out[(size_t)(b0 + b) * Osz + tid] = oacc[b] * inv;
    }
}

// ---------------- launch -----------------------------------------------------------------
extern "C" void kernel_launch(void* const* d_in, const int* in_sizes, int n_in,
                              void* d_out, int out_size) {
    const float* x    = (const float*)d_in[0];
    const float* h0   = (const float*)d_in[1];
    const float* W_ih = (const float*)d_in[2];
    const float* b_ih = (const float*)d_in[3];
    const float* W_hh = (const float*)d_in[4];
    const float* b_hh = (const float*)d_in[5];
    const float* Wt   = (const float*)d_in[6];
    const float* bt   = (const float*)d_in[7];
    const float* Wo   = (const float*)d_in[8];
    const float* bo   = (const float*)d_in[9];
    const float* Wg   = (const float*)d_in[10];
    const float* bg   = (const float*)d_in[11];
    float* out = (float*)d_out;

    const int GEMM_SMEM = (128 + 128) * XSTR * 2;          // 69632
    const int SCAN_SMEM = 61952 + NTC * 16 * 32 * 8;       // 225792
    cudaFuncSetAttribute(gemm_xi, cudaFuncAttributeMaxDynamicSharedMemorySize, GEMM_SMEM);
    cudaFuncSetAttribute(gru_scan, cudaFuncAttributeMaxDynamicSharedMemorySize, SCAN_SMEM);

    pack_wh<<<(1024 * Isz / 8 + 255) / 256, 256>>>(W_ih, Wt);
    prep_whhf<<<(96 * 16 * 32 + 255) / 256, 256>>>(W_hh);
    prep_wof<<<(16 * 16 * 32 + 255) / 256, 256>>>(Wo, Wg);
    gemm_xi<<<(Bsz * Tsz) / 128, 256, GEMM_SMEM>>>(x, b_ih, bt);
    gru_scan<<<NCTA, STHR, SCAN_SMEM>>>(h0, b_hh, bo, bg, out);
}

// round 12
// speedup vs baseline: 1.5272x; 1.2063x over previous
#include <cuda_runtime.h>
#include <cuda_fp16.h>

typedef unsigned long long ull;
typedef unsigned int uint;

#define Bsz 1024
#define Tsz 512
#define Isz 128
#define Hsz 256
#define Osz 64
#define NBc 16      // batches per cluster
#define NCTA 128    // 64 clusters x 2
#define STHR 512
#define XSTR 136    // gemm smem row stride (halves)
#define HSTR 264    // h16/v16 row stride (halves): conflict-free ldmatrix

// ---------------- device scratch -----------------------------------------------------
// g_xi layout [b][t][1024]: 0..255 xr, 256..511 xz, 512..767 xn (+b_ih), 768..1023 silu
__device__ __half g_xi[(size_t)Bsz * Tsz * 1024];    // 1.07 GB
__device__ __half g_wh[(size_t)1024 * Isz];          // [W_ih;Wt] fp16 for prepass
__device__ uint2  g_Whf[96 * 16 * 32];               // W_hh fragment-major fp16 (393 KB)
__device__ uint2  g_Wof[16 * 16 * 32];               // [Wo;Wg] fragment-major fp16 (64 KB)

// ---------------- scan smem layout (bytes) --------------------------------------------
#define SM_H16(p)  ((p) * 8448)            // [2][16][HSTR] f16
#define SM_V16(p)  (16896 + (p) * 8448)    // [2][16][HSTR] f16
#define SM_H32     33792                   // [16][128] f32 (own j-half)
#define SM_HH      41984                   // [16][392] f32 (own 384 cols + pad)
#define SM_XI      67072                   // [16][512] f16 (own 4x128 cols)
#define SM_REDP    83456                   // [2][16][64] f32
#define SM_TOTAL   91648

// ---------------- helpers --------------------------------------------------------------
__device__ __forceinline__ float sigmf(float x) { return 1.0f / (1.0f + __expf(-x)); }
__device__ __forceinline__ float tanhf_(float x) {
    float a = fabsf(x);
    float e = __expf(-2.0f * a);
    return copysignf((1.0f - e) / (1.0f + e), x);
}
__device__ __forceinline__ uint smem_u32(const void* p) {
    uint a;
    asm("{ .reg .u64 t; cvta.to.shared.u64 t, %1; cvt.u32.u64 %0, t; }" : "=r"(a) : "l"(p));
    return a;
}
__device__ __forceinline__ void ldm_x4(uint* a, const __half* p) {
    uint addr = smem_u32(p);
    asm volatile("ldmatrix.sync.aligned.m8n8.x4.shared.b16 {%0,%1,%2,%3}, [%4];"
                 : "=r"(a[0]), "=r"(a[1]), "=r"(a[2]), "=r"(a[3]) : "r"(addr));
}
__device__ __forceinline__ void ldm_x2(uint* b, const __half* p) {
    uint addr = smem_u32(p);
    asm volatile("ldmatrix.sync.aligned.m8n8.x2.shared.b16 {%0,%1}, [%2];"
                 : "=r"(b[0]), "=r"(b[1]) : "r"(addr));
}
__device__ __forceinline__ void mma16816(float* d, const uint* a, const uint* b) {
    asm volatile(
        "mma.sync.aligned.m16n8k16.row.col.f32.f16.f16.f32 "
        "{%0,%1,%2,%3}, {%4,%5,%6,%7}, {%8,%9}, {%0,%1,%2,%3};"
        : "+f"(d[0]), "+f"(d[1]), "+f"(d[2]), "+f"(d[3])
        : "r"(a[0]), "r"(a[1]), "r"(a[2]), "r"(a[3]), "r"(b[0]), "r"(b[1]));
}
__device__ __forceinline__ uint mapa_u32(uint addr, uint rank) {
    uint r;
    asm("mapa.shared::cluster.u32 %0, %1, %2;" : "=r"(r) : "r"(addr), "r"(rank));
    return r;
}
__device__ __forceinline__ void st_remote_u32(uint addr, uint v) {
    asm volatile("st.shared::cluster.u32 [%0], %1;" :: "r"(addr), "r"(v) : "memory");
}
#define CLUSTER_SYNC() do { \
    asm volatile("barrier.cluster.arrive.aligned;" ::: "memory"); \
    asm volatile("barrier.cluster.wait.aligned;" ::: "memory"); \
} while (0)

// ---------------- packing kernels -------------------------------------------------------
__global__ void pack_wh(const float* __restrict__ Wih, const float* __restrict__ Wt) {
    int i = blockIdx.x * blockDim.x + threadIdx.x;
    if (i >= (1024 * Isz) / 8) return;
    int row = i >> 4, q = i & 15;
    const float* s = (row < 768) ? (Wih + (size_t)row * Isz + q * 8)
                                 : (Wt + (size_t)(row - 768) * Isz + q * 8);
    float4 f0 = __ldg((const float4*)s), f1 = __ldg((const float4*)s + 1);
    __half2 h0 = __floats2half2_rn(f0.x, f0.y), h1 = __floats2half2_rn(f0.z, f0.w);
    __half2 h2 = __floats2half2_rn(f1.x, f1.y), h3 = __floats2half2_rn(f1.z, f1.w);
    *(uint4*)(g_wh + (size_t)i * 8) =
        make_uint4(*(uint*)&h0, *(uint*)&h1, *(uint*)&h2, *(uint*)&h3);
}
__global__ void prep_whhf(const float* __restrict__ Whh) {
    int idx = blockIdx.x * blockDim.x + threadIdx.x;
    if (idx >= 96 * 16 * 32) return;
    int lane = idx & 31, kt = (idx >> 5) & 15, nt = idx >> 9;
    int n = nt * 8 + (lane >> 2);
    int k0 = kt * 16 + (lane & 3) * 2;
    const float* s = Whh + (size_t)n * Hsz;
    __half2 lo = __floats2half2_rn(s[k0], s[k0 + 1]);
    __half2 hi = __floats2half2_rn(s[k0 + 8], s[k0 + 9]);
    g_Whf[idx] = make_uint2(*(uint*)&lo, *(uint*)&hi);
}
__global__ void prep_wof(const float* __restrict__ Wo, const float* __restrict__ Wg) {
    int idx = blockIdx.x * blockDim.x + threadIdx.x;
    if (idx >= 16 * 16 * 32) return;
    int lane = idx & 31, kt = (idx >> 5) & 15, nt = idx >> 9;
    int n = nt * 8 + (lane >> 2);
    int k0 = kt * 16 + (lane & 3) * 2;
    const float* s = (n < 64) ? (Wo + (size_t)n * Hsz) : (Wg + (size_t)(n - 64) * Hsz);
    __half2 lo = __floats2half2_rn(s[k0], s[k0 + 1]);
    __half2 hi = __floats2half2_rn(s[k0 + 8], s[k0 + 9]);
    g_Wof[idx] = make_uint2(*(uint*)&lo, *(uint*)&hi);
}

// ---------------- HMMA prepass GEMM (unchanged from R11) -------------------------------
__global__ void __launch_bounds__(256, 2) gemm_xi(const float* __restrict__ x,
                                                  const float* __restrict__ b_ih,
                                                  const float* __restrict__ bt) {
    extern __shared__ __align__(16) __half sh[];
    __half* Xs = sh;                  // [128][XSTR]
    __half* Ws = sh + 128 * XSTR;     // [128][XSTR]

    const int tid = threadIdx.x, wid = tid >> 5, lane = tid & 31;
    const int rbase0 = blockIdx.x * 128;
    const int wm = wid & 1, wn = wid >> 1;

#pragma unroll
    for (int i = tid; i < 2048; i += 256) {
        int row = i >> 4, q = i & 15;
        const float4* s = (const float4*)(x + (size_t)(rbase0 + row) * Isz + q * 8);
        float4 f0 = __ldg(s), f1 = __ldg(s + 1);
        __half2 h0 = __floats2half2_rn(f0.x, f0.y), h1 = __floats2half2_rn(f0.z, f0.w);
        __half2 h2 = __floats2half2_rn(f1.x, f1.y), h3 = __floats2half2_rn(f1.z, f1.w);
        *(uint4*)(Xs + row * XSTR + q * 8) =
            make_uint4(*(uint*)&h0, *(uint*)&h1, *(uint*)&h2, *(uint*)&h3);
    }

    for (int chunk = 0; chunk < 8; ++chunk) {
        {
            const uint4* src = (const uint4*)(g_wh + (size_t)chunk * 128 * Isz);
#pragma unroll
            for (int i = tid; i < 2048; i += 256) {
                int row = i >> 4, q = i & 15;
                *(uint4*)(Ws + row * XSTR + q * 8) = __ldg(src + row * 16 + q);
            }
        }
        __syncthreads();

        float acc[4][4][4];
#pragma unroll
        for (int mf = 0; mf < 4; ++mf)
#pragma unroll
            for (int nf = 0; nf < 4; ++nf)
#pragma unroll
                for (int q = 0; q < 4; ++q) acc[mf][nf][q] = 0.0f;

#pragma unroll
        for (int k = 0; k < 8; ++k) {
            uint a[4][4];
#pragma unroll
            for (int mf = 0; mf < 4; ++mf)
                ldm_x4(a[mf], Xs + (wm * 64 + mf * 16 + (lane & 15)) * XSTR
                                 + k * 16 + (lane >> 4) * 8);
            uint bf[4][2];
#pragma unroll
            for (int nf = 0; nf < 4; ++nf)
                ldm_x2(bf[nf], Ws + (wn * 32 + nf * 8 + (lane & 7)) * XSTR
                                  + k * 16 + ((lane >> 3) & 1) * 8);
#pragma unroll
            for (int mf = 0; mf < 4; ++mf)
#pragma unroll
                for (int nf = 0; nf < 4; ++nf)
                    mma16816(acc[mf][nf], a[mf], bf[nf]);
        }

        const bool do_silu = (chunk >= 6);
#pragma unroll
        for (int nf = 0; nf < 4; ++nf) {
            int c = chunk * 128 + wn * 32 + nf * 8 + (lane & 3) * 2;
            float bias0, bias1;
            if (!do_silu) { bias0 = __ldg(b_ih + c); bias1 = __ldg(b_ih + c + 1); }
            else          { bias0 = __ldg(bt + c - 768); bias1 = __ldg(bt + c - 767); }
#pragma unroll
            for (int mf = 0; mf < 4; ++mf) {
                int r1 = rbase0 + wm * 64 + mf * 16 + (lane >> 2);
#pragma unroll
                for (int h = 0; h < 2; ++h) {
                    int rr = r1 + h * 8;
                    float v0 = acc[mf][nf][2 * h]     + bias0;
                    float v1 = acc[mf][nf][2 * h + 1] + bias1;
                    if (do_silu) { v0 *= sigmf(v0); v1 *= sigmf(v1); }
                    *(__half2*)(g_xi + (size_t)rr * 1024 + c) = __floats2half2_rn(v0, v1);
                }
            }
        }
        __syncthreads();
    }
}

// ---------------- clustered GRU scan: 64 clusters x 2 CTAs, split-N recurrence ---------
__global__ void __launch_bounds__(STHR, 1) __cluster_dims__(2, 1, 1)
gru_scan(const float* __restrict__ h0, const float* __restrict__ b_hh,
         const float* __restrict__ bo, const float* __restrict__ bg,
         float* __restrict__ out)
{
    extern __shared__ __align__(16) char smraw[];
    const uint smb = smem_u32(smraw);

    const int tid  = threadIdx.x;
    const int w    = tid >> 5, lane = tid & 31;
    const int r    = blockIdx.x & 1;          // cluster CTA rank
    const int b0   = (blockIdx.x >> 1) * NBc; // batch base for this cluster
    const uint rsmb = mapa_u32(smb, (uint)(r ^ 1));  // peer smem base

    // ---- phase C thread mapping ----
    const int jp  = tid & 63, j0 = 2 * jp;    // local even hidden-pair
    const int grp = tid >> 6;                  // batches {grp, grp+8}
    const int jg  = 128 * r + j0;              // global hidden index

    // ---- phase B warp mapping: 3 n-tiles per warp (own 48 of 96) ----
    const int ntA = 16 * r + w, ntB = 32 + 16 * r + w, ntC = 64 + 16 * r + w;

    // ---- phase D warp mapping ----
    const int wl = w & 7, kh2 = w >> 3;
    const bool isG = (wl >= 4);
    const int ntD = isG ? (8 + 4 * r + (wl & 3)) : (4 * r + (wl & 3));
    const int colD = (isG ? 32 : 0) + (wl & 3) * 8 + 2 * (lane & 3);

    { // init h16[0] (full 16 batches) and h32 (own j-half)
        int b = tid >> 5, k0 = (tid & 31) * 8;
        const float4* p = (const float4*)(h0 + (size_t)(b0 + b) * Hsz + k0);
        float4 v0 = p[0], v1 = p[1];
        __half2 a0 = __floats2half2_rn(v0.x, v0.y), a1 = __floats2half2_rn(v0.z, v0.w);
        __half2 a2 = __floats2half2_rn(v1.x, v1.y), a3 = __floats2half2_rn(v1.z, v1.w);
        *(uint4*)(smraw + SM_H16(0) + (b * HSTR + k0) * 2) =
            make_uint4(*(uint*)&a0, *(uint*)&a1, *(uint*)&a2, *(uint*)&a3);
        // own j-half of h32: cols [128r, 128r+128)
        int kq = (tid & 31) * 4;
        if (kq < 128) {
            float4 hv = *(const float4*)(h0 + (size_t)(b0 + b) * Hsz + 128 * r + kq);
            *(float4*)(smraw + SM_H32 + (b * 128 + kq) * 4) = hv;
        }
    }

    const float2 hbr2 = *(const float2*)(b_hh + jg);
    const float2 hbz2 = *(const float2*)(b_hh + Hsz + jg);
    const float2 hbn2 = *(const float2*)(b_hh + 2 * Hsz + jg);
    const float boT = __ldg(bo + 32 * r + (tid & 31));
    const float bgT = __ldg(bg + 32 * r + (tid & 31));
    float oacc = 0.0f;   // thread owns (b = tid>>5, c = tid&31)

    __syncthreads();
    CLUSTER_SYNC();

    for (int t = 0; t < Tsz; ++t) {
        const int p = t & 1;
        __half* h16p  = (__half*)(smraw + SM_H16(p));
        __half* h16n  = (__half*)(smraw + SM_H16(p ^ 1));
        __half* v16n  = (__half*)(smraw + SM_V16(p ^ 1));
        __half* xi_s  = (__half*)(smraw + SM_XI);
        float*  hh    = (float*)(smraw + SM_HH);
        float*  h32   = (float*)(smraw + SM_H32);
        float*  redP  = (float*)(smraw + SM_REDP);

        { // stage own xi cols: 16 b x 4 segs x 128 halves = 16 KB
#pragma unroll
            for (int ii = 0; ii < 2; ++ii) {
                int i = tid + 512 * ii;
                int pair = i >> 4, q = i & 15;       // pair = b*4 + seg
                int b = pair >> 2, seg = pair & 3;
                const uint4* src = (const uint4*)(g_xi +
                    ((size_t)(b0 + b) * Tsz + t) * 1024 + seg * 256 + 128 * r) + q;
                *((uint4*)(xi_s + b * 512 + seg * 128) + q) = __ldg(src);
            }
        }

        // ---- Phase B: hh(own 384 cols) = h(16b) @ W_hh^T, M=16 HMMA ----
        {
            const __half* aB = h16p + (lane & 15) * HSTR + (lane >> 4) * 8;
            float acc[3][4];
#pragma unroll
            for (int i = 0; i < 3; ++i)
#pragma unroll
                for (int q = 0; q < 4; ++q) acc[i][q] = 0.0f;
#pragma unroll
            for (int kt = 0; kt < 16; ++kt) {
                uint a[4];
                ldm_x4(a, aB + kt * 16);
                uint2 f0 = __ldg(&g_Whf[(ntA * 16 + kt) * 32 + lane]);
                uint2 f1 = __ldg(&g_Whf[(ntB * 16 + kt) * 32 + lane]);
                uint2 f2 = __ldg(&g_Whf[(ntC * 16 + kt) * 32 + lane]);
                mma16816(acc[0], a, (uint*)&f0);
                mma16816(acc[1], a, (uint*)&f1);
                mma16816(acc[2], a, (uint*)&f2);
            }
            const int bb = lane >> 2, cc = w * 8 + 2 * (lane & 3);
#pragma unroll
            for (int g = 0; g < 3; ++g) {
                *(float2*)&hh[bb * 392 + g * 128 + cc] = make_float2(acc[g][0], acc[g][1]);
                *(float2*)&hh[(bb + 8) * 392 + g * 128 + cc] =
                    make_float2(acc[g][2], acc[g][3]);
            }
        }
        __syncthreads();  // bar1: hh + xi ready

        // ---- Phase C: gates + update for own j-half; writes local + remote ----
#pragma unroll
        for (int q = 0; q < 2; ++q) {
            const int b = grp + 8 * q;
            const __half2* xp = (const __half2*)(xi_s + b * 512 + j0);
            float2 xr = __half22float2(xp[0]);
            float2 xz = __half22float2(xp[64]);    // +128 halves
            float2 xn = __half22float2(xp[128]);   // +256
            float2 xt = __half22float2(xp[192]);   // +384
            const float* hhb = hh + b * 392;
            float2 hr = *(const float2*)(hhb + j0);
            float2 hz = *(const float2*)(hhb + 128 + j0);
            float2 hn = *(const float2*)(hhb + 256 + j0);
            float2 hp = *(const float2*)(h32 + b * 128 + j0);

            float r0 = sigmf(xr.x + hr.x + hbr2.x);
            float r1 = sigmf(xr.y + hr.y + hbr2.y);
            float z0 = sigmf(xz.x + hz.x + hbz2.x);
            float z1 = sigmf(xz.y + hz.y + hbz2.y);
            float n0 = tanhf_(xn.x + r0 * (hn.x + hbn2.x));
            float n1 = tanhf_(xn.y + r1 * (hn.y + hbn2.y));
            float h0n = n0 + z0 * (hp.x - n0);
            float h1n = n1 + z1 * (hp.y - n1);
            *(float2*)(h32 + b * 128 + j0) = make_float2(h0n, h1n);

            __half2 hh2 = __floats2half2_rn(h0n, h1n);
            __half2 vv2 = __floats2half2_rn(h0n + xt.x, h1n + xt.y);
            const uint off_h = (uint)SM_H16(p ^ 1) + (b * HSTR + jg) * 2;
            const uint off_v = (uint)SM_V16(p ^ 1) + (b * HSTR + jg) * 2;
            *(__half2*)(smraw + off_h) = hh2;
            *(__half2*)(smraw + off_v) = vv2;
            st_remote_u32(rsmb + off_h, *(uint*)&hh2);
            st_remote_u32(rsmb + off_v, *(uint*)&vv2);
        }
        CLUSTER_SYNC();   // all C writes (local + remote) visible cluster-wide

        // ---- Phase D: own 32 proj + 32 gate cols, split-K 2-way ----
        {
            const __half* aD = (isG ? h16n : v16n) + (lane & 15) * HSTR + (lane >> 4) * 8;
            float acc[4] = {0.f, 0.f, 0.f, 0.f};
#pragma unroll
            for (int ki = 0; ki < 8; ++ki) {
                const int kt = kh2 * 8 + ki;
                uint a[4];
                ldm_x4(a, aD + kt * 16);
                uint2 wf = __ldg(&g_Wof[(ntD * 16 + kt) * 32 + lane]);
                mma16816(acc, a, (uint*)&wf);
            }
            const int bb = lane >> 2;
            *(float2*)&redP[kh2 * 1024 + bb * 64 + colD] = make_float2(acc[0], acc[1]);
            *(float2*)&redP[kh2 * 1024 + (bb + 8) * 64 + colD] =
                make_float2(acc[2], acc[3]);
        }
        __syncthreads();  // bar3: redP ready

        { // finalize: thread owns (b = tid>>5, c = tid&31)
            const int b = tid >> 5, c = tid & 31;
            float pr = redP[b * 64 + c] + redP[1024 + b * 64 + c] + boT;
            float gt = redP[b * 64 + 32 + c] + redP[1024 + b * 64 + 32 + c] + bgT;
            oacc += pr * sigmf(gt);
        }
    }

    { // output: CTA r writes cols [32r, 32r+32)
        const int b = tid >> 5, c = tid & 31;
        out[(size_t)(b0 + b) * Osz + 32 * r + c] = oacc * (1.0f / (float)Tsz);
    }
    CLUSTER_SYNC();   // keep smem alive until peer's remote writes are done
}

// ---------------- launch -----------------------------------------------------------------
extern "C" void kernel_launch(void* const* d_in, const int* in_sizes, int n_in,
                              void* d_out, int out_size) {
    const float* x    = (const float*)d_in[0];
    const float* h0   = (const float*)d_in[1];
    const float* W_ih = (const float*)d_in[2];
    const float* b_ih = (const float*)d_in[3];
    const float* W_hh = (const float*)d_in[4];
    const float* b_hh = (const float*)d_in[5];
    const float* Wt   = (const float*)d_in[6];
    const float* bt   = (const float*)d_in[7];
    const float* Wo   = (const float*)d_in[8];
    const float* bo   = (const float*)d_in[9];
    const float* Wg   = (const float*)d_in[10];
    const float* bg   = (const float*)d_in[11];
    float* out = (float*)d_out;

    const int GEMM_SMEM = (128 + 128) * XSTR * 2;   // 69632
    cudaFuncSetAttribute(gemm_xi, cudaFuncAttributeMaxDynamicSharedMemorySize, GEMM_SMEM);
    cudaFuncSetAttribute(gru_scan, cudaFuncAttributeMaxDynamicSharedMemorySize, SM_TOTAL);

    pack_wh<<<(1024 * Isz / 8 + 255) / 256, 256>>>(W_ih, Wt);
    prep_whhf<<<(96 * 16 * 32 + 255) / 256, 256>>>(W_hh);
    prep_wof<<<(16 * 16 * 32 + 255) / 256, 256>>>(Wo, Wg);
    gemm_xi<<<(Bsz * Tsz) / 128, 256, GEMM_SMEM>>>(x, b_ih, bt);
    gru_scan<<<NCTA, STHR, SM_TOTAL>>>(h0, b_hh, bo, bg, out);
}

// round 13
// speedup vs baseline: 1.6662x; 1.0910x over previous
#include <cuda_runtime.h>
#include <cuda_fp16.h>

typedef unsigned long long ull;
typedef unsigned int uint;

#define Bsz 1024
#define Tsz 512
#define Isz 128
#define Hsz 256
#define Osz 64
#define NBc 16      // batches per cluster
#define NCTA 128    // 64 clusters x 2
#define STHR 512
#define XSTR 136    // gemm smem row stride (halves)
#define HSTR 264    // h16/v16 row stride (halves): conflict-free ldmatrix

// ---------------- device scratch -----------------------------------------------------
// g_xi layout [b][t][1024]: 0..255 xr, 256..511 xz, 512..767 xn (+b_ih), 768..1023 silu
__device__ __half g_xi[(size_t)Bsz * Tsz * 1024];    // 1.07 GB
__device__ __half g_wh[(size_t)1024 * Isz];          // [W_ih;Wt] fp16 for prepass
__device__ uint2  g_Whf[96 * 16 * 32];               // W_hh fragment-major fp16 (393 KB)
__device__ uint2  g_Wof[16 * 16 * 32];               // [Wo;Wg] fragment-major fp16 (64 KB)

// ---------------- scan smem layout (bytes) --------------------------------------------
#define SM_H16(p)  ((p) * 8448)            // [2][16][HSTR] f16
#define SM_V16(p)  (16896 + (p) * 8448)    // [2][16][HSTR] f16
#define SM_H32     33792                   // [16][128] f32 (own j-half)
#define SM_HH      41984                   // [16][392] f32 (own 384 cols + pad)
#define SM_XI      67072                   // [16][512] f16 (own 4x128 cols)
#define SM_REDP    83456                   // [2][16][64] f32
#define SM_TOTAL   91648

// ---------------- helpers --------------------------------------------------------------
__device__ __forceinline__ float sigmf(float x) { return 1.0f / (1.0f + __expf(-x)); }
__device__ __forceinline__ float tanhf_(float x) {
    float a = fabsf(x);
    float e = __expf(-2.0f * a);
    return copysignf((1.0f - e) / (1.0f + e), x);
}
__device__ __forceinline__ uint smem_u32(const void* p) {
    uint a;
    asm("{ .reg .u64 t; cvta.to.shared.u64 t, %1; cvt.u32.u64 %0, t; }" : "=r"(a) : "l"(p));
    return a;
}
__device__ __forceinline__ void ldm_x4(uint* a, const __half* p) {
    uint addr = smem_u32(p);
    asm volatile("ldmatrix.sync.aligned.m8n8.x4.shared.b16 {%0,%1,%2,%3}, [%4];"
                 : "=r"(a[0]), "=r"(a[1]), "=r"(a[2]), "=r"(a[3]) : "r"(addr));
}
__device__ __forceinline__ void ldm_x2(uint* b, const __half* p) {
    uint addr = smem_u32(p);
    asm volatile("ldmatrix.sync.aligned.m8n8.x2.shared.b16 {%0,%1}, [%2];"
                 : "=r"(b[0]), "=r"(b[1]) : "r"(addr));
}
__device__ __forceinline__ void mma16816(float* d, const uint* a, const uint* b) {
    asm volatile(
        "mma.sync.aligned.m16n8k16.row.col.f32.f16.f16.f32 "
        "{%0,%1,%2,%3}, {%4,%5,%6,%7}, {%8,%9}, {%0,%1,%2,%3};"
        : "+f"(d[0]), "+f"(d[1]), "+f"(d[2]), "+f"(d[3])
        : "r"(a[0]), "r"(a[1]), "r"(a[2]), "r"(a[3]), "r"(b[0]), "r"(b[1]));
}
__device__ __forceinline__ uint mapa_u32(uint addr, uint rank) {
    uint r;
    asm("mapa.shared::cluster.u32 %0, %1, %2;" : "=r"(r) : "r"(addr), "r"(rank));
    return r;
}
__device__ __forceinline__ void st_remote_u32(uint addr, uint v) {
    asm volatile("st.shared::cluster.u32 [%0], %1;" :: "r"(addr), "r"(v) : "memory");
}
#define CLUSTER_SYNC() do { \
    asm volatile("barrier.cluster.arrive.aligned;" ::: "memory"); \
    asm volatile("barrier.cluster.wait.aligned;" ::: "memory"); \
} while (0)

// ---------------- packing kernels -------------------------------------------------------
__global__ void pack_wh(const float* __restrict__ Wih, const float* __restrict__ Wt) {
    int i = blockIdx.x * blockDim.x + threadIdx.x;
    if (i >= (1024 * Isz) / 8) return;
    int row = i >> 4, q = i & 15;
    const float* s = (row < 768) ? (Wih + (size_t)row * Isz + q * 8)
                                 : (Wt + (size_t)(row - 768) * Isz + q * 8);
    float4 f0 = __ldg((const float4*)s), f1 = __ldg((const float4*)s + 1);
    __half2 h0 = __floats2half2_rn(f0.x, f0.y), h1 = __floats2half2_rn(f0.z, f0.w);
    __half2 h2 = __floats2half2_rn(f1.x, f1.y), h3 = __floats2half2_rn(f1.z, f1.w);
    *(uint4*)(g_wh + (size_t)i * 8) =
        make_uint4(*(uint*)&h0, *(uint*)&h1, *(uint*)&h2, *(uint*)&h3);
}
__global__ void prep_whhf(const float* __restrict__ Whh) {
    int idx = blockIdx.x * blockDim.x + threadIdx.x;
    if (idx >= 96 * 16 * 32) return;
    int lane = idx & 31, kt = (idx >> 5) & 15, nt = idx >> 9;
    int n = nt * 8 + (lane >> 2);
    int k0 = kt * 16 + (lane & 3) * 2;
    const float* s = Whh + (size_t)n * Hsz;
    __half2 lo = __floats2half2_rn(s[k0], s[k0 + 1]);
    __half2 hi = __floats2half2_rn(s[k0 + 8], s[k0 + 9]);
    g_Whf[idx] = make_uint2(*(uint*)&lo, *(uint*)&hi);
}
__global__ void prep_wof(const float* __restrict__ Wo, const float* __restrict__ Wg) {
    int idx = blockIdx.x * blockDim.x + threadIdx.x;
    if (idx >= 16 * 16 * 32) return;
    int lane = idx & 31, kt = (idx >> 5) & 15, nt = idx >> 9;
    int n = nt * 8 + (lane >> 2);
    int k0 = kt * 16 + (lane & 3) * 2;
    const float* s = (n < 64) ? (Wo + (size_t)n * Hsz) : (Wg + (size_t)(n - 64) * Hsz);
    __half2 lo = __floats2half2_rn(s[k0], s[k0 + 1]);
    __half2 hi = __floats2half2_rn(s[k0 + 8], s[k0 + 9]);
    g_Wof[idx] = make_uint2(*(uint*)&lo, *(uint*)&hi);
}

// ---------------- HMMA prepass GEMM: smem-transposed epilogue ---------------------------
__global__ void __launch_bounds__(256, 2) gemm_xi(const float* __restrict__ x,
                                                  const float* __restrict__ b_ih,
                                                  const float* __restrict__ bt) {
    extern __shared__ __align__(16) __half sh[];
    __half* Xs = sh;                  // [128][XSTR]
    __half* Ws = sh + 128 * XSTR;     // [128][XSTR]; reused as epilogue buffer

    const int tid = threadIdx.x, wid = tid >> 5, lane = tid & 31;
    const int rbase0 = blockIdx.x * 128;
    const int wm = wid & 1, wn = wid >> 1;   // 2x4: 64 rows x 32 cols per warp

#pragma unroll
    for (int i = tid; i < 2048; i += 256) {
        int row = i >> 4, q = i & 15;
        const float4* s = (const float4*)(x + (size_t)(rbase0 + row) * Isz + q * 8);
        float4 f0 = __ldg(s), f1 = __ldg(s + 1);
        __half2 h0 = __floats2half2_rn(f0.x, f0.y), h1 = __floats2half2_rn(f0.z, f0.w);
        __half2 h2 = __floats2half2_rn(f1.x, f1.y), h3 = __floats2half2_rn(f1.z, f1.w);
        *(uint4*)(Xs + row * XSTR + q * 8) =
            make_uint4(*(uint*)&h0, *(uint*)&h1, *(uint*)&h2, *(uint*)&h3);
    }

    for (int chunk = 0; chunk < 8; ++chunk) {
        { // stage W chunk (128 cols of [W_ih;Wt])
            const uint4* src = (const uint4*)(g_wh + (size_t)chunk * 128 * Isz);
#pragma unroll
            for (int i = tid; i < 2048; i += 256) {
                int row = i >> 4, q = i & 15;
                *(uint4*)(Ws + row * XSTR + q * 8) = __ldg(src + row * 16 + q);
            }
        }
        __syncthreads();   // Ws staged (and Xs on first iter)

        float acc[4][4][4];
#pragma unroll
        for (int mf = 0; mf < 4; ++mf)
#pragma unroll
            for (int nf = 0; nf < 4; ++nf)
#pragma unroll
                for (int q = 0; q < 4; ++q) acc[mf][nf][q] = 0.0f;

#pragma unroll
        for (int k = 0; k < 8; ++k) {
            uint a[4][4];
#pragma unroll
            for (int mf = 0; mf < 4; ++mf)
                ldm_x4(a[mf], Xs + (wm * 64 + mf * 16 + (lane & 15)) * XSTR
                                 + k * 16 + (lane >> 4) * 8);
            uint bf[4][2];
#pragma unroll
            for (int nf = 0; nf < 4; ++nf)
                ldm_x2(bf[nf], Ws + (wn * 32 + nf * 8 + (lane & 7)) * XSTR
                                  + k * 16 + ((lane >> 3) & 1) * 8);
#pragma unroll
            for (int mf = 0; mf < 4; ++mf)
#pragma unroll
                for (int nf = 0; nf < 4; ++nf)
                    mma16816(acc[mf][nf], a[mf], bf[nf]);
        }
        __syncthreads();   // all mma reads of Ws done -> Ws reusable

        // epilogue stage 1: bias(+silu), STS into Ws (conflict-free fragment scatter)
        const bool do_silu = (chunk >= 6);
#pragma unroll
        for (int nf = 0; nf < 4; ++nf) {
            int cl = wn * 32 + nf * 8 + (lane & 3) * 2;   // chunk-local col
            int cg = chunk * 128 + cl;
            float bias0, bias1;
            if (!do_silu) { bias0 = __ldg(b_ih + cg); bias1 = __ldg(b_ih + cg + 1); }
            else          { bias0 = __ldg(bt + cg - 768); bias1 = __ldg(bt + cg - 767); }
#pragma unroll
            for (int mf = 0; mf < 4; ++mf) {
#pragma unroll
                for (int h = 0; h < 2; ++h) {
                    int rl = wm * 64 + mf * 16 + (lane >> 2) + h * 8;
                    float v0 = acc[mf][nf][2 * h]     + bias0;
                    float v1 = acc[mf][nf][2 * h + 1] + bias1;
                    if (do_silu) { v0 *= sigmf(v0); v1 *= sigmf(v1); }
                    *(__half2*)(Ws + rl * XSTR + cl) = __floats2half2_rn(v0, v1);
                }
            }
        }
        __syncthreads();   // transpose buffer complete

        // epilogue stage 2: coalesced LDS.128 + STG.128
#pragma unroll
        for (int ii = 0; ii < 8; ++ii) {
            int idx = tid + 256 * ii;
            int row = idx >> 4, q = idx & 15;
            uint4 v = *(uint4*)(Ws + row * XSTR + q * 8);
            *(uint4*)(g_xi + (size_t)(rbase0 + row) * 1024 + chunk * 128 + q * 8) = v;
        }
        __syncthreads();   // reads of Ws done before next chunk stages it
    }
}

// ---------------- clustered GRU scan: 64 clusters x 2 CTAs, reg-cached fragments --------
__global__ void __launch_bounds__(STHR, 1) __cluster_dims__(2, 1, 1)
gru_scan(const float* __restrict__ h0, const float* __restrict__ b_hh,
         const float* __restrict__ bo, const float* __restrict__ bg,
         float* __restrict__ out)
{
    extern __shared__ __align__(16) char smraw[];
    const uint smb = smem_u32(smraw);

    const int tid  = threadIdx.x;
    const int w    = tid >> 5, lane = tid & 31;
    const int r    = blockIdx.x & 1;          // cluster CTA rank
    const int b0   = (blockIdx.x >> 1) * NBc; // batch base for this cluster
    const uint rsmb = mapa_u32(smb, (uint)(r ^ 1));  // peer smem base

    // ---- phase C thread mapping ----
    const int jp  = tid & 63, j0 = 2 * jp;    // local even hidden-pair
    const int grp = tid >> 6;                  // batches {grp, grp+8}
    const int jg  = 128 * r + j0;              // global hidden index

    // ---- phase B warp mapping: 3 n-tiles per warp (own 48 of 96) ----
    const int ntA = 16 * r + w, ntB = 32 + 16 * r + w, ntC = 64 + 16 * r + w;

    // ---- phase D warp mapping ----
    const int wl = w & 7, kh2 = w >> 3;
    const bool isG = (wl >= 4);
    const int ntD = isG ? (8 + 4 * r + (wl & 3)) : (4 * r + (wl & 3));
    const int colD = (isG ? 32 : 0) + (wl & 3) * 8 + 2 * (lane & 3);

    { // init h16[0] (full 16 batches) and h32 (own j-half)
        int b = tid >> 5, k0 = (tid & 31) * 8;
        const float4* p = (const float4*)(h0 + (size_t)(b0 + b) * Hsz + k0);
        float4 v0 = p[0], v1 = p[1];
        __half2 a0 = __floats2half2_rn(v0.x, v0.y), a1 = __floats2half2_rn(v0.z, v0.w);
        __half2 a2 = __floats2half2_rn(v1.x, v1.y), a3 = __floats2half2_rn(v1.z, v1.w);
        *(uint4*)(smraw + SM_H16(0) + (b * HSTR + k0) * 2) =
            make_uint4(*(uint*)&a0, *(uint*)&a1, *(uint*)&a2, *(uint*)&a3);
        int kq = (tid & 31) * 4;
        if (kq < 128) {
            float4 hv = *(const float4*)(h0 + (size_t)(b0 + b) * Hsz + 128 * r + kq);
            *(float4*)(smraw + SM_H32 + (b * 128 + kq) * 4) = hv;
        }
    }

    // ---- register-cached invariant fragments (immune to cluster.sync L1 flush) ----
    uint2 wfa[16];
#pragma unroll
    for (int kt = 0; kt < 16; ++kt)
        wfa[kt] = __ldg(&g_Whf[(ntA * 16 + kt) * 32 + lane]);
    uint2 wofr[8];
#pragma unroll
    for (int ki = 0; ki < 8; ++ki)
        wofr[ki] = __ldg(&g_Wof[(ntD * 16 + kh2 * 8 + ki) * 32 + lane]);

    const float2 hbr2 = *(const float2*)(b_hh + jg);
    const float2 hbz2 = *(const float2*)(b_hh + Hsz + jg);
    const float2 hbn2 = *(const float2*)(b_hh + 2 * Hsz + jg);
    const float boT = __ldg(bo + 32 * r + (tid & 31));
    const float bgT = __ldg(bg + 32 * r + (tid & 31));
    float oacc = 0.0f;   // thread owns (b = tid>>5, c = tid&31)

    __syncthreads();
    CLUSTER_SYNC();

    for (int t = 0; t < Tsz; ++t) {
        const int p = t & 1;
        __half* h16p  = (__half*)(smraw + SM_H16(p));
        __half* h16n  = (__half*)(smraw + SM_H16(p ^ 1));
        __half* v16n  = (__half*)(smraw + SM_V16(p ^ 1));
        __half* xi_s  = (__half*)(smraw + SM_XI);
        float*  hh    = (float*)(smraw + SM_HH);
        float*  h32   = (float*)(smraw + SM_H32);
        float*  redP  = (float*)(smraw + SM_REDP);

        { // stage own xi cols: 16 b x 4 segs x 128 halves = 16 KB
#pragma unroll
            for (int ii = 0; ii < 2; ++ii) {
                int i = tid + 512 * ii;
                int pair = i >> 4, q = i & 15;       // pair = b*4 + seg
                int b = pair >> 2, seg = pair & 3;
                const uint4* src = (const uint4*)(g_xi +
                    ((size_t)(b0 + b) * Tsz + t) * 1024 + seg * 256 + 128 * r) + q;
                *((uint4*)(xi_s + b * 512 + seg * 128) + q) = __ldg(src);
            }
        }

        // ---- Phase B: hh(own 384 cols) = h(16b) @ W_hh^T; ntA from regs, B/C pipelined --
        {
            const __half* aB = h16p + (lane & 15) * HSTR + (lane >> 4) * 8;
            float acc0[4] = {0.f, 0.f, 0.f, 0.f};
            float acc1[4] = {0.f, 0.f, 0.f, 0.f};
            float acc2[4] = {0.f, 0.f, 0.f, 0.f};
            uint2 fb[2], fc[2];
            fb[0] = __ldg(&g_Whf[(ntB * 16 + 0) * 32 + lane]);
            fc[0] = __ldg(&g_Whf[(ntC * 16 + 0) * 32 + lane]);
            fb[1] = __ldg(&g_Whf[(ntB * 16 + 1) * 32 + lane]);
            fc[1] = __ldg(&g_Whf[(ntC * 16 + 1) * 32 + lane]);
#pragma unroll
            for (int kt = 0; kt < 16; ++kt) {
                const int s = kt & 1;
                uint a[4];
                ldm_x4(a, aB + kt * 16);
                uint2 cb = fb[s], cc2 = fc[s];
                if (kt + 2 < 16) {
                    fb[s] = __ldg(&g_Whf[(ntB * 16 + kt + 2) * 32 + lane]);
                    fc[s] = __ldg(&g_Whf[(ntC * 16 + kt + 2) * 32 + lane]);
                }
                mma16816(acc0, a, (uint*)&wfa[kt]);
                mma16816(acc1, a, (uint*)&cb);
                mma16816(acc2, a, (uint*)&cc2);
            }
            const int bb = lane >> 2, cc = w * 8 + 2 * (lane & 3);
            *(float2*)&hh[bb * 392 + cc]         = make_float2(acc0[0], acc0[1]);
            *(float2*)&hh[(bb + 8) * 392 + cc]   = make_float2(acc0[2], acc0[3]);
            *(float2*)&hh[bb * 392 + 128 + cc]       = make_float2(acc1[0], acc1[1]);
            *(float2*)&hh[(bb + 8) * 392 + 128 + cc] = make_float2(acc1[2], acc1[3]);
            *(float2*)&hh[bb * 392 + 256 + cc]       = make_float2(acc2[0], acc2[1]);
            *(float2*)&hh[(bb + 8) * 392 + 256 + cc] = make_float2(acc2[2], acc2[3]);
        }
        __syncthreads();  // bar1: hh + xi ready

        // ---- Phase C: gates + update for own j-half; writes local + remote ----
#pragma unroll
        for (int q = 0; q < 2; ++q) {
            const int b = grp + 8 * q;
            const __half2* xp = (const __half2*)(xi_s + b * 512 + j0);
            float2 xr = __half22float2(xp[0]);
            float2 xz = __half22float2(xp[64]);
            float2 xn = __half22float2(xp[128]);
            float2 xt = __half22float2(xp[192]);
            const float* hhb = hh + b * 392;
            float2 hr = *(const float2*)(hhb + j0);
            float2 hz = *(const float2*)(hhb + 128 + j0);
            float2 hn = *(const float2*)(hhb + 256 + j0);
            float2 hp = *(const float2*)(h32 + b * 128 + j0);

            float r0 = sigmf(xr.x + hr.x + hbr2.x);
            float r1 = sigmf(xr.y + hr.y + hbr2.y);
            float z0 = sigmf(xz.x + hz.x + hbz2.x);
            float z1 = sigmf(xz.y + hz.y + hbz2.y);
            float n0 = tanhf_(xn.x + r0 * (hn.x + hbn2.x));
            float n1 = tanhf_(xn.y + r1 * (hn.y + hbn2.y));
            float h0n = n0 + z0 * (hp.x - n0);
            float h1n = n1 + z1 * (hp.y - n1);
            *(float2*)(h32 + b * 128 + j0) = make_float2(h0n, h1n);

            __half2 hh2 = __floats2half2_rn(h0n, h1n);
            __half2 vv2 = __floats2half2_rn(h0n + xt.x, h1n + xt.y);
            const uint off_h = (uint)SM_H16(p ^ 1) + (b * HSTR + jg) * 2;
            const uint off_v = (uint)SM_V16(p ^ 1) + (b * HSTR + jg) * 2;
            *(__half2*)(smraw + off_h) = hh2;
            *(__half2*)(smraw + off_v) = vv2;
            st_remote_u32(rsmb + off_h, *(uint*)&hh2);
            st_remote_u32(rsmb + off_v, *(uint*)&vv2);
        }
        CLUSTER_SYNC();   // all C writes (local + remote) visible cluster-wide

        // ---- Phase D: own 32 proj + 32 gate cols, fragments from registers ----
        {
            const __half* aD = (isG ? h16n : v16n) + (lane & 15) * HSTR + (lane >> 4) * 8;
            float acc[4] = {0.f, 0.f, 0.f, 0.f};
#pragma unroll
            for (int ki = 0; ki < 8; ++ki) {
                const int kt = kh2 * 8 + ki;
                uint a[4];
                ldm_x4(a, aD + kt * 16);
                mma16816(acc, a, (uint*)&wofr[ki]);
            }
            const int bb = lane >> 2;
            *(float2*)&redP[kh2 * 1024 + bb * 64 + colD] = make_float2(acc[0], acc[1]);
            *(float2*)&redP[kh2 * 1024 + (bb + 8) * 64 + colD] =
                make_float2(acc[2], acc[3]);
        }
        __syncthreads();  // bar3: redP ready

        { // finalize: thread owns (b = tid>>5, c = tid&31)
            const int b = tid >> 5, c = tid & 31;
            float pr = redP[b * 64 + c] + redP[1024 + b * 64 + c] + boT;
            float gt = redP[b * 64 + 32 + c] + redP[1024 + b * 64 + 32 + c] + bgT;
            oacc += pr * sigmf(gt);
        }
    }

    { // output: CTA r writes cols [32r, 32r+32)
        const int b = tid >> 5, c = tid & 31;
        out[(size_t)(b0 + b) * Osz + 32 * r + c] = oacc * (1.0f / (float)Tsz);
    }
    CLUSTER_SYNC();   // keep smem alive until peer's remote writes are done
}

// ---------------- launch -----------------------------------------------------------------
extern "C" void kernel_launch(void* const* d_in, const int* in_sizes, int n_in,
                              void* d_out, int out_size) {
    const float* x    = (const float*)d_in[0];
    const float* h0   = (const float*)d_in[1];
    const float* W_ih = (const float*)d_in[2];
    const float* b_ih = (const float*)d_in[3];
    const float* W_hh = (const float*)d_in[4];
    const float* b_hh = (const float*)d_in[5];
    const float* Wt   = (const float*)d_in[6];
    const float* bt   = (const float*)d_in[7];
    const float* Wo   = (const float*)d_in[8];
    const float* bo   = (const float*)d_in[9];
    const float* Wg   = (const float*)d_in[10];
    const float* bg   = (const float*)d_in[11];
    float* out = (float*)d_out;

    const int GEMM_SMEM = (128 + 128) * XSTR * 2;   // 69632
    cudaFuncSetAttribute(gemm_xi, cudaFuncAttributeMaxDynamicSharedMemorySize, GEMM_SMEM);
    cudaFuncSetAttribute(gru_scan, cudaFuncAttributeMaxDynamicSharedMemorySize, SM_TOTAL);

    pack_wh<<<(1024 * Isz / 8 + 255) / 256, 256>>>(W_ih, Wt);
    prep_whhf<<<(96 * 16 * 32 + 255) / 256, 256>>>(W_hh);
    prep_wof<<<(16 * 16 * 32 + 255) / 256, 256>>>(Wo, Wg);
    gemm_xi<<<(Bsz * Tsz) / 128, 256, GEMM_SMEM>>>(x, b_ih, bt);
    gru_scan<<<NCTA, STHR, SM_TOTAL>>>(h0, b_hh, bo, bg, out);
}

// round 14
// speedup vs baseline: 1.8091x; 1.0857x over previous
#include <cuda_runtime.h>
#include <cuda_fp16.h>

typedef unsigned long long ull;
typedef unsigned int uint;

#define Bsz 1024
#define Tsz 512
#define Isz 128
#define Hsz 256
#define Osz 64
#define NBc 16      // batches per cluster
#define NCTA 128    // 64 clusters x 2
#define STHR 512
#define XSTR 136    // gemm smem row stride (halves)
#define HSTR 264    // h16/v16 row stride (halves): conflict-free ldmatrix

// ---------------- device scratch -----------------------------------------------------
// g_xi layout [b][t][1024]: 0..255 xr, 256..511 xz, 512..767 xn (+b_ih), 768..1023 silu
__device__ __half g_xi[(size_t)Bsz * Tsz * 1024];    // 1.07 GB
__device__ __half g_wh[(size_t)1024 * Isz];          // [W_ih;Wt] fp16 for prepass
__device__ uint2  g_Whf[96 * 16 * 32];               // W_hh fragment-major fp16 (393 KB)
__device__ uint2  g_Wof[16 * 16 * 32];               // [Wo;Wg] fragment-major fp16 (64 KB)

// ---------------- scan smem layout (bytes) --------------------------------------------
#define SM_H16(p)  ((p) * 8448)            // [2][16][HSTR] f16
#define SM_V16(p)  (16896 + (p) * 8448)    // [2][16][HSTR] f16
#define SM_H32     33792                   // [16][128] f32 (own j-half)
#define SM_HH      41984                   // [16][392] f32 (own 384 cols + pad)
#define SM_XI      67072                   // [16][512] f16 (own 4x128 cols)
#define SM_REDP    83456                   // [2][16][64] f32
#define SM_MBAR    91648                   // mbarrier (8 B)
#define SM_TOTAL   91664
#define TX_BYTES   8192u                   // 512 thr x 4 st.async x 4 B

// ---------------- helpers --------------------------------------------------------------
__device__ __forceinline__ float sigmf(float x) { return 1.0f / (1.0f + __expf(-x)); }
__device__ __forceinline__ float tanhf_(float x) {
    float a = fabsf(x);
    float e = __expf(-2.0f * a);
    return copysignf((1.0f - e) / (1.0f + e), x);
}
__device__ __forceinline__ uint smem_u32(const void* p) {
    uint a;
    asm("{ .reg .u64 t; cvta.to.shared.u64 t, %1; cvt.u32.u64 %0, t; }" : "=r"(a) : "l"(p));
    return a;
}
__device__ __forceinline__ void ldm_x4(uint* a, const __half* p) {
    uint addr = smem_u32(p);
    asm volatile("ldmatrix.sync.aligned.m8n8.x4.shared.b16 {%0,%1,%2,%3}, [%4];"
                 : "=r"(a[0]), "=r"(a[1]), "=r"(a[2]), "=r"(a[3]) : "r"(addr));
}
__device__ __forceinline__ void ldm_x2(uint* b, const __half* p) {
    uint addr = smem_u32(p);
    asm volatile("ldmatrix.sync.aligned.m8n8.x2.shared.b16 {%0,%1}, [%2];"
                 : "=r"(b[0]), "=r"(b[1]) : "r"(addr));
}
__device__ __forceinline__ void mma16816(float* d, const uint* a, const uint* b) {
    asm volatile(
        "mma.sync.aligned.m16n8k16.row.col.f32.f16.f16.f32 "
        "{%0,%1,%2,%3}, {%4,%5,%6,%7}, {%8,%9}, {%0,%1,%2,%3};"
        : "+f"(d[0]), "+f"(d[1]), "+f"(d[2]), "+f"(d[3])
        : "r"(a[0]), "r"(a[1]), "r"(a[2]), "r"(a[3]), "r"(b[0]), "r"(b[1]));
}
__device__ __forceinline__ uint mapa_u32(uint addr, uint rank) {
    uint r;
    asm("mapa.shared::cluster.u32 %0, %1, %2;" : "=r"(r) : "r"(addr), "r"(rank));
    return r;
}
// remote smem store with mbarrier transaction tracking (peer's mbar)
__device__ __forceinline__ void st_async_u32(uint raddr, uint v, uint rmbar) {
    asm volatile(
        "st.async.weak.shared::cluster.mbarrier::complete_tx::bytes.b32 [%0], %1, [%2];"
        :: "r"(raddr), "r"(v), "r"(rmbar) : "memory");
}
__device__ __forceinline__ void mbar_init(uint mb, uint cnt) {
    asm volatile("mbarrier.init.shared.b64 [%0], %1;" :: "r"(mb), "r"(cnt) : "memory");
}
__device__ __forceinline__ void mbar_expect_tx(uint mb, uint bytes) {
    asm volatile("mbarrier.arrive.expect_tx.shared.b64 _, [%0], %1;"
                 :: "r"(mb), "r"(bytes) : "memory");
}
__device__ __forceinline__ void mbar_wait(uint mb, uint parity) {
    asm volatile(
        "{\n\t.reg .pred P;\n\tW%=:\n\t"
        "mbarrier.try_wait.parity.shared.b64 P, [%0], %1;\n\t"
        "@!P bra W%=;\n\t}"
        :: "r"(mb), "r"(parity) : "memory");
}
#define CLUSTER_SYNC() do { \
    asm volatile("barrier.cluster.arrive.aligned;" ::: "memory"); \
    asm volatile("barrier.cluster.wait.aligned;" ::: "memory"); \
} while (0)
__device__ __forceinline__ void cp_async16(uint daddr, const void* src) {
    asm volatile("cp.async.cg.shared.global [%0], [%1], 16;" :: "r"(daddr), "l"(src));
}
#define CP_COMMIT() asm volatile("cp.async.commit_group;" ::: "memory")
#define CP_WAIT(n)  asm volatile("cp.async.wait_group %0;" :: "n"(n) : "memory")

// ---------------- packing kernels -------------------------------------------------------
__global__ void pack_wh(const float* __restrict__ Wih, const float* __restrict__ Wt) {
    int i = blockIdx.x * blockDim.x + threadIdx.x;
    if (i >= (1024 * Isz) / 8) return;
    int row = i >> 4, q = i & 15;
    const float* s = (row < 768) ? (Wih + (size_t)row * Isz + q * 8)
                                 : (Wt + (size_t)(row - 768) * Isz + q * 8);
    float4 f0 = __ldg((const float4*)s), f1 = __ldg((const float4*)s + 1);
    __half2 h0 = __floats2half2_rn(f0.x, f0.y), h1 = __floats2half2_rn(f0.z, f0.w);
    __half2 h2 = __floats2half2_rn(f1.x, f1.y), h3 = __floats2half2_rn(f1.z, f1.w);
    *(uint4*)(g_wh + (size_t)i * 8) =
        make_uint4(*(uint*)&h0, *(uint*)&h1, *(uint*)&h2, *(uint*)&h3);
}
__global__ void prep_whhf(const float* __restrict__ Whh) {
    int idx = blockIdx.x * blockDim.x + threadIdx.x;
    if (idx >= 96 * 16 * 32) return;
    int lane = idx & 31, kt = (idx >> 5) & 15, nt = idx >> 9;
    int n = nt * 8 + (lane >> 2);
    int k0 = kt * 16 + (lane & 3) * 2;
    const float* s = Whh + (size_t)n * Hsz;
    __half2 lo = __floats2half2_rn(s[k0], s[k0 + 1]);
    __half2 hi = __floats2half2_rn(s[k0 + 8], s[k0 + 9]);
    g_Whf[idx] = make_uint2(*(uint*)&lo, *(uint*)&hi);
}
__global__ void prep_wof(const float* __restrict__ Wo, const float* __restrict__ Wg) {
    int idx = blockIdx.x * blockDim.x + threadIdx.x;
    if (idx >= 16 * 16 * 32) return;
    int lane = idx & 31, kt = (idx >> 5) & 15, nt = idx >> 9;
    int n = nt * 8 + (lane >> 2);
    int k0 = kt * 16 + (lane & 3) * 2;
    const float* s = (n < 64) ? (Wo + (size_t)n * Hsz) : (Wg + (size_t)(n - 64) * Hsz);
    __half2 lo = __floats2half2_rn(s[k0], s[k0 + 1]);
    __half2 hi = __floats2half2_rn(s[k0 + 8], s[k0 + 9]);
    g_Wof[idx] = make_uint2(*(uint*)&lo, *(uint*)&hi);
}

// ---------------- HMMA prepass GEMM: cp.async double-buffered W, 64-row CTAs ------------
__global__ void __launch_bounds__(256, 2) gemm_xi(const float* __restrict__ x,
                                                  const float* __restrict__ b_ih,
                                                  const float* __restrict__ bt) {
    extern __shared__ __align__(16) __half sh[];
    __half* Xs  = sh;                        // [64][XSTR]
    __half* Ws0 = sh + 64 * XSTR;            // [128][XSTR]
    __half* Ws1 = Ws0 + 128 * XSTR;          // [128][XSTR]
    __half* Es  = Ws1 + 128 * XSTR;          // [64][XSTR] epilogue transpose buffer

    const int tid = threadIdx.x, lane = tid & 31;
    const int wid = tid >> 5;
    const int rbase0 = blockIdx.x * 64;
    const int wm = wid & 1, wn = wid >> 1;   // 2x4: 32 rows x 32 cols per warp

    { // stage X tile: 64 rows, fp32 -> fp16 fused
#pragma unroll
        for (int i = tid; i < 1024; i += 256) {
            int row = i >> 4, q = i & 15;
            const float4* s = (const float4*)(x + (size_t)(rbase0 + row) * Isz + q * 8);
            float4 f0 = __ldg(s), f1 = __ldg(s + 1);
            __half2 h0 = __floats2half2_rn(f0.x, f0.y), h1 = __floats2half2_rn(f0.z, f0.w);
            __half2 h2 = __floats2half2_rn(f1.x, f1.y), h3 = __floats2half2_rn(f1.z, f1.w);
            *(uint4*)(Xs + row * XSTR + q * 8) =
                make_uint4(*(uint*)&h0, *(uint*)&h1, *(uint*)&h2, *(uint*)&h3);
        }
    }

    // prologue: async-stage W chunk 0
    {
        __half* Wd = Ws0;
#pragma unroll
        for (int i = tid; i < 2048; i += 256) {
            int row = i >> 4, q = i & 15;
            cp_async16(smem_u32(Wd + row * XSTR + q * 8),
                       g_wh + (size_t)0 * 128 * Isz + (size_t)i * 8);
        }
        CP_COMMIT();
    }

    for (int chunk = 0; chunk < 8; ++chunk) {
        __half* Wc = (chunk & 1) ? Ws1 : Ws0;
        if (chunk < 7) { // stage next chunk into alternate buffer
            __half* Wd = (chunk & 1) ? Ws0 : Ws1;
            const char* src = (const char*)(g_wh + (size_t)(chunk + 1) * 128 * Isz);
#pragma unroll
            for (int i = tid; i < 2048; i += 256) {
                int row = i >> 4, q = i & 15;
                cp_async16(smem_u32(Wd + row * XSTR + q * 8), src + (size_t)i * 16);
            }
            CP_COMMIT();
            CP_WAIT(1);
        } else {
            CP_WAIT(0);
        }
        __syncthreads();   // Wc visible to all warps

        float acc[2][4][4];
#pragma unroll
        for (int mf = 0; mf < 2; ++mf)
#pragma unroll
            for (int nf = 0; nf < 4; ++nf)
#pragma unroll
                for (int q = 0; q < 4; ++q) acc[mf][nf][q] = 0.0f;

#pragma unroll
        for (int k = 0; k < 8; ++k) {
            uint a[2][4];
#pragma unroll
            for (int mf = 0; mf < 2; ++mf)
                ldm_x4(a[mf], Xs + (wm * 32 + mf * 16 + (lane & 15)) * XSTR
                                 + k * 16 + (lane >> 4) * 8);
            uint bf[4][2];
#pragma unroll
            for (int nf = 0; nf < 4; ++nf)
                ldm_x2(bf[nf], Wc + (wn * 32 + nf * 8 + (lane & 7)) * XSTR
                                  + k * 16 + ((lane >> 3) & 1) * 8);
#pragma unroll
            for (int mf = 0; mf < 2; ++mf)
#pragma unroll
                for (int nf = 0; nf < 4; ++nf)
                    mma16816(acc[mf][nf], a[mf], bf[nf]);
        }

        // epilogue stage 1: bias(+silu), STS transpose into Es
        const bool do_silu = (chunk >= 6);
#pragma unroll
        for (int nf = 0; nf < 4; ++nf) {
            int cl = wn * 32 + nf * 8 + (lane & 3) * 2;
            int cg = chunk * 128 + cl;
            float bias0, bias1;
            if (!do_silu) { bias0 = __ldg(b_ih + cg); bias1 = __ldg(b_ih + cg + 1); }
            else          { bias0 = __ldg(bt + cg - 768); bias1 = __ldg(bt + cg - 767); }
#pragma unroll
            for (int mf = 0; mf < 2; ++mf) {
#pragma unroll
                for (int h = 0; h < 2; ++h) {
                    int rl = wm * 32 + mf * 16 + (lane >> 2) + h * 8;
                    float v0 = acc[mf][nf][2 * h]     + bias0;
                    float v1 = acc[mf][nf][2 * h + 1] + bias1;
                    if (do_silu) { v0 *= sigmf(v0); v1 *= sigmf(v1); }
                    *(__half2*)(Es + rl * XSTR + cl) = __floats2half2_rn(v0, v1);
                }
            }
        }
        __syncthreads();   // Es complete

        // epilogue stage 2: coalesced LDS.128 + STG.128
#pragma unroll
        for (int ii = 0; ii < 4; ++ii) {
            int idx = tid + 256 * ii;
            int row = idx >> 4, q = idx & 15;
            uint4 v = *(uint4*)(Es + row * XSTR + q * 8);
            *(uint4*)(g_xi + (size_t)(rbase0 + row) * 1024 + chunk * 128 + q * 8) = v;
        }
        __syncthreads();   // Es + Wc reads done before next iteration
    }
}

// ---------------- clustered GRU scan: st.async handshake, warm L1 -----------------------
__global__ void __launch_bounds__(STHR, 1) __cluster_dims__(2, 1, 1)
gru_scan(const float* __restrict__ h0, const float* __restrict__ b_hh,
         const float* __restrict__ bo, const float* __restrict__ bg,
         float* __restrict__ out)
{
    extern __shared__ __align__(16) char smraw[];
    const uint smb = smem_u32(smraw);

    const int tid  = threadIdx.x;
    const int w    = tid >> 5, lane = tid & 31;
    const int r    = blockIdx.x & 1;          // cluster CTA rank
    const int b0   = (blockIdx.x >> 1) * NBc; // batch base for this cluster
    const uint rsmb = mapa_u32(smb, (uint)(r ^ 1));  // peer smem base
    const uint mb   = smb + SM_MBAR;                 // local mbarrier
    const uint rmb  = rsmb + SM_MBAR;                // peer mbarrier

    // ---- phase C thread mapping ----
    const int jp  = tid & 63, j0 = 2 * jp;
    const int grp = tid >> 6;                  // batches {grp, grp+8}
    const int jg  = 128 * r + j0;

    // ---- phase B warp mapping: 3 n-tiles per warp (own 48 of 96) ----
    const int ntA = 16 * r + w, ntB = 32 + 16 * r + w, ntC = 64 + 16 * r + w;

    // ---- phase D warp mapping ----
    const int wl = w & 7, kh2 = w >> 3;
    const bool isG = (wl >= 4);
    const int ntD = isG ? (8 + 4 * r + (wl & 3)) : (4 * r + (wl & 3));
    const int colD = (isG ? 32 : 0) + (wl & 3) * 8 + 2 * (lane & 3);

    { // init h16[0] (full 16 batches) and h32 (own j-half)
        int b = tid >> 5, k0 = (tid & 31) * 8;
        const float4* p = (const float4*)(h0 + (size_t)(b0 + b) * Hsz + k0);
        float4 v0 = p[0], v1 = p[1];
        __half2 a0 = __floats2half2_rn(v0.x, v0.y), a1 = __floats2half2_rn(v0.z, v0.w);
        __half2 a2 = __floats2half2_rn(v1.x, v1.y), a3 = __floats2half2_rn(v1.z, v1.w);
        *(uint4*)(smraw + SM_H16(0) + (b * HSTR + k0) * 2) =
            make_uint4(*(uint*)&a0, *(uint*)&a1, *(uint*)&a2, *(uint*)&a3);
        int kq = (tid & 31) * 4;
        if (kq < 128) {
            float4 hv = *(const float4*)(h0 + (size_t)(b0 + b) * Hsz + 128 * r + kq);
            *(float4*)(smraw + SM_H32 + (b * 128 + kq) * 4) = hv;
        }
    }
    if (tid == 0) mbar_init(mb, 1);

    // ---- register-cached invariant fragments ----
    uint2 wfa[16];
#pragma unroll
    for (int kt = 0; kt < 16; ++kt)
        wfa[kt] = __ldg(&g_Whf[(ntA * 16 + kt) * 32 + lane]);
    uint2 wofr[8];
#pragma unroll
    for (int ki = 0; ki < 8; ++ki)
        wofr[ki] = __ldg(&g_Wof[(ntD * 16 + kh2 * 8 + ki) * 32 + lane]);

    const float2 hbr2 = *(const float2*)(b_hh + jg);
    const float2 hbz2 = *(const float2*)(b_hh + Hsz + jg);
    const float2 hbn2 = *(const float2*)(b_hh + 2 * Hsz + jg);
    const float boT = __ldg(bo + 32 * r + (tid & 31));
    const float bgT = __ldg(bg + 32 * r + (tid & 31));
    float oacc = 0.0f;

    __syncthreads();
    CLUSTER_SYNC();   // mbarrier init + h16[0] visible cluster-wide

    for (int t = 0; t < Tsz; ++t) {
        const int p = t & 1;
        __half* h16p  = (__half*)(smraw + SM_H16(p));
        __half* h16n  = (__half*)(smraw + SM_H16(p ^ 1));
        __half* v16n  = (__half*)(smraw + SM_V16(p ^ 1));
        __half* xi_s  = (__half*)(smraw + SM_XI);
        float*  hh    = (float*)(smraw + SM_HH);
        float*  h32   = (float*)(smraw + SM_H32);
        float*  redP  = (float*)(smraw + SM_REDP);

        if (tid == 0) mbar_expect_tx(mb, TX_BYTES);

        { // stage own xi cols: 16 b x 4 segs x 128 halves = 16 KB
#pragma unroll
            for (int ii = 0; ii < 2; ++ii) {
                int i = tid + 512 * ii;
                int pair = i >> 4, q = i & 15;
                int b = pair >> 2, seg = pair & 3;
                const uint4* src = (const uint4*)(g_xi +
                    ((size_t)(b0 + b) * Tsz + t) * 1024 + seg * 256 + 128 * r) + q;
                *((uint4*)(xi_s + b * 512 + seg * 128) + q) = __ldg(src);
            }
        }

        // ---- Phase B: hh(own 384 cols) = h(16b) @ W_hh^T; ntA regs, B/C L1-warm ----
        {
            const __half* aB = h16p + (lane & 15) * HSTR + (lane >> 4) * 8;
            float acc0[4] = {0.f, 0.f, 0.f, 0.f};
            float acc1[4] = {0.f, 0.f, 0.f, 0.f};
            float acc2[4] = {0.f, 0.f, 0.f, 0.f};
            uint2 fb[2], fc[2];
            fb[0] = __ldg(&g_Whf[(ntB * 16 + 0) * 32 + lane]);
            fc[0] = __ldg(&g_Whf[(ntC * 16 + 0) * 32 + lane]);
            fb[1] = __ldg(&g_Whf[(ntB * 16 + 1) * 32 + lane]);
            fc[1] = __ldg(&g_Whf[(ntC * 16 + 1) * 32 + lane]);
#pragma unroll
            for (int kt = 0; kt < 16; ++kt) {
                const int s = kt & 1;
                uint a[4];
                ldm_x4(a, aB + kt * 16);
                uint2 cb = fb[s], cc2 = fc[s];
                if (kt + 2 < 16) {
                    fb[s] = __ldg(&g_Whf[(ntB * 16 + kt + 2) * 32 + lane]);
                    fc[s] = __ldg(&g_Whf[(ntC * 16 + kt + 2) * 32 + lane]);
                }
                mma16816(acc0, a, (uint*)&wfa[kt]);
                mma16816(acc1, a, (uint*)&cb);
                mma16816(acc2, a, (uint*)&cc2);
            }
            const int bb = lane >> 2, cc = w * 8 + 2 * (lane & 3);
            *(float2*)&hh[bb * 392 + cc]         = make_float2(acc0[0], acc0[1]);
            *(float2*)&hh[(bb + 8) * 392 + cc]   = make_float2(acc0[2], acc0[3]);
            *(float2*)&hh[bb * 392 + 128 + cc]       = make_float2(acc1[0], acc1[1]);
            *(float2*)&hh[(bb + 8) * 392 + 128 + cc] = make_float2(acc1[2], acc1[3]);
            *(float2*)&hh[bb * 392 + 256 + cc]       = make_float2(acc2[0], acc2[1]);
            *(float2*)&hh[(bb + 8) * 392 + 256 + cc] = make_float2(acc2[2], acc2[3]);
        }
        __syncthreads();  // bar1: hh + xi ready

        // ---- Phase C: gates + update for own j-half; remote via st.async ----
#pragma unroll
        for (int q = 0; q < 2; ++q) {
            const int b = grp + 8 * q;
            const __half2* xp = (const __half2*)(xi_s + b * 512 + j0);
            float2 xr = __half22float2(xp[0]);
            float2 xz = __half22float2(xp[64]);
            float2 xn = __half22float2(xp[128]);
            float2 xt = __half22float2(xp[192]);
            const float* hhb = hh + b * 392;
            float2 hr = *(const float2*)(hhb + j0);
            float2 hz = *(const float2*)(hhb + 128 + j0);
            float2 hn = *(const float2*)(hhb + 256 + j0);
            float2 hp = *(const float2*)(h32 + b * 128 + j0);

            float r0 = sigmf(xr.x + hr.x + hbr2.x);
            float r1 = sigmf(xr.y + hr.y + hbr2.y);
            float z0 = sigmf(xz.x + hz.x + hbz2.x);
            float z1 = sigmf(xz.y + hz.y + hbz2.y);
            float n0 = tanhf_(xn.x + r0 * (hn.x + hbn2.x));
            float n1 = tanhf_(xn.y + r1 * (hn.y + hbn2.y));
            float h0n = n0 + z0 * (hp.x - n0);
            float h1n = n1 + z1 * (hp.y - n1);
            *(float2*)(h32 + b * 128 + j0) = make_float2(h0n, h1n);

            __half2 hh2 = __floats2half2_rn(h0n, h1n);
            __half2 vv2 = __floats2half2_rn(h0n + xt.x, h1n + xt.y);
            const uint off_h = (uint)SM_H16(p ^ 1) + (b * HSTR + jg) * 2;
            const uint off_v = (uint)SM_V16(p ^ 1) + (b * HSTR + jg) * 2;
            *(__half2*)(smraw + off_h) = hh2;
            *(__half2*)(smraw + off_v) = vv2;
            st_async_u32(rsmb + off_h, *(uint*)&hh2, rmb);
            st_async_u32(rsmb + off_v, *(uint*)&vv2, rmb);
        }
        __syncthreads();      // local C writes visible CTA-wide
        mbar_wait(mb, (uint)(t & 1));   // peer's st.async halves arrived

        // ---- Phase D: own 32 proj + 32 gate cols, fragments from registers ----
        {
            const __half* aD = (isG ? h16n : v16n) + (lane & 15) * HSTR + (lane >> 4) * 8;
            float acc[4] = {0.f, 0.f, 0.f, 0.f};
#pragma unroll
            for (int ki = 0; ki < 8; ++ki) {
                const int kt = kh2 * 8 + ki;
                uint a[4];
                ldm_x4(a, aD + kt * 16);
                mma16816(acc, a, (uint*)&wofr[ki]);
            }
            const int bb = lane >> 2;
            *(float2*)&redP[kh2 * 1024 + bb * 64 + colD] = make_float2(acc[0], acc[1]);
            *(float2*)&redP[kh2 * 1024 + (bb + 8) * 64 + colD] =
                make_float2(acc[2], acc[3]);
        }
        __syncthreads();  // bar3: redP ready

        { // finalize: thread owns (b = tid>>5, c = tid&31)
            const int b = tid >> 5, c = tid & 31;
            float pr = redP[b * 64 + c] + redP[1024 + b * 64 + c] + boT;
            float gt = redP[b * 64 + 32 + c] + redP[1024 + b * 64 + 32 + c] + bgT;
            oacc += pr * sigmf(gt);
        }
    }

    { // output: CTA r writes cols [32r, 32r+32)
        const int b = tid >> 5, c = tid & 31;
        out[(size_t)(b0 + b) * Osz + 32 * r + c] = oacc * (1.0f / (float)Tsz);
    }
    CLUSTER_SYNC();   // keep smem alive until peer fully drained
}

// ---------------- launch -----------------------------------------------------------------
extern "C" void kernel_launch(void* const* d_in, const int* in_sizes, int n_in,
                              void* d_out, int out_size) {
    const float* x    = (const float*)d_in[0];
    const float* h0   = (const float*)d_in[1];
    const float* W_ih = (const float*)d_in[2];
    const float* b_ih = (const float*)d_in[3];
    const float* W_hh = (const float*)d_in[4];
    const float* b_hh = (const float*)d_in[5];
    const float* Wt   = (const float*)d_in[6];
    const float* bt   = (const float*)d_in[7];
    const float* Wo   = (const float*)d_in[8];
    const float* bo   = (const float*)d_in[9];
    const float* Wg   = (const float*)d_in[10];
    const float* bg   = (const float*)d_in[11];
    float* out = (float*)d_out;

    const int GEMM_SMEM = (64 + 128 + 128 + 64) * XSTR * 2;   // 104448
    cudaFuncSetAttribute(gemm_xi, cudaFuncAttributeMaxDynamicSharedMemorySize, GEMM_SMEM);
    cudaFuncSetAttribute(gru_scan, cudaFuncAttributeMaxDynamicSharedMemorySize, SM_TOTAL);

    pack_wh<<<(1024 * Isz / 8 + 255) / 256, 256>>>(W_ih, Wt);
    prep_whhf<<<(96 * 16 * 32 + 255) / 256, 256>>>(W_hh);
    prep_wof<<<(16 * 16 * 32 + 255) / 256, 256>>>(Wo, Wg);
    gemm_xi<<<(Bsz * Tsz) / 64, 256, GEMM_SMEM>>>(x, b_ih, bt);
    gru_scan<<<NCTA, STHR, SM_TOTAL>>>(h0, b_hh, bo, bg, out);
}

// round 15
// speedup vs baseline: 1.8540x; 1.0249x over previous
#include <cuda_runtime.h>
#include <cuda_fp16.h>

typedef unsigned long long ull;
typedef unsigned int uint;

#define Bsz 1024
#define Tsz 512
#define Isz 128
#define Hsz 256
#define Osz 64
#define NBc 16      // batches per cluster
#define NCTA 128    // 64 clusters x 2
#define STHR 512
#define XSTR 136    // gemm smem row stride (halves)
#define HSTR 264    // h16/v16 row stride (halves): conflict-free ldmatrix

// ---------------- device scratch -----------------------------------------------------
// g_xi layout [b][t][1024]: 0..255 xr, 256..511 xz, 512..767 xn (+b_ih), 768..1023 silu
__device__ __half g_xi[(size_t)Bsz * Tsz * 1024];    // 1.07 GB
__device__ __half g_wh[(size_t)1024 * Isz];          // [W_ih;Wt] fp16 for prepass
__device__ uint2  g_Whf[96 * 16 * 32];               // W_hh fragment-major fp16 (393 KB)
__device__ uint2  g_Wof[16 * 16 * 32];               // [Wo;Wg] fragment-major fp16 (64 KB)

// ---------------- scan smem layout (bytes) --------------------------------------------
#define SM_H16(p)  ((p) * 8448)            // [2][16][HSTR] f16
#define SM_V16(p)  (16896 + (p) * 8448)    // [2][16][HSTR] f16
#define SM_H32     33792                   // [16][128] f32 (own j-half)
#define SM_HH      41984                   // [16][392] f32 (own 384 cols + pad)
#define SM_XI      67072                   // [16][512] f16 (own 4x128 cols)
#define SM_REDP    83456                   // [16][64] f32
#define SM_MBAR    87552                   // mbarrier (8 B)
#define SM_TOTAL   87568
#define TX_BYTES   8192u                   // 512 thr x 4 st.async x 4 B

// ---------------- helpers --------------------------------------------------------------
__device__ __forceinline__ float sigmf(float x) { return 1.0f / (1.0f + __expf(-x)); }
__device__ __forceinline__ float tanhf_(float x) {
    float a = fabsf(x);
    float e = __expf(-2.0f * a);
    return copysignf((1.0f - e) / (1.0f + e), x);
}
__device__ __forceinline__ uint smem_u32(const void* p) {
    uint a;
    asm("{ .reg .u64 t; cvta.to.shared.u64 t, %1; cvt.u32.u64 %0, t; }" : "=r"(a) : "l"(p));
    return a;
}
__device__ __forceinline__ void ldm_x4(uint* a, const __half* p) {
    uint addr = smem_u32(p);
    asm volatile("ldmatrix.sync.aligned.m8n8.x4.shared.b16 {%0,%1,%2,%3}, [%4];"
                 : "=r"(a[0]), "=r"(a[1]), "=r"(a[2]), "=r"(a[3]) : "r"(addr));
}
__device__ __forceinline__ void ldm_x2(uint* b, const __half* p) {
    uint addr = smem_u32(p);
    asm volatile("ldmatrix.sync.aligned.m8n8.x2.shared.b16 {%0,%1}, [%2];"
                 : "=r"(b[0]), "=r"(b[1]) : "r"(addr));
}
__device__ __forceinline__ void mma16816(float* d, const uint* a, const uint* b) {
    asm volatile(
        "mma.sync.aligned.m16n8k16.row.col.f32.f16.f16.f32 "
        "{%0,%1,%2,%3}, {%4,%5,%6,%7}, {%8,%9}, {%0,%1,%2,%3};"
        : "+f"(d[0]), "+f"(d[1]), "+f"(d[2]), "+f"(d[3])
        : "r"(a[0]), "r"(a[1]), "r"(a[2]), "r"(a[3]), "r"(b[0]), "r"(b[1]));
}
__device__ __forceinline__ uint mapa_u32(uint addr, uint rank) {
    uint r;
    asm("mapa.shared::cluster.u32 %0, %1, %2;" : "=r"(r) : "r"(addr), "r"(rank));
    return r;
}
__device__ __forceinline__ void st_async_u32(uint raddr, uint v, uint rmbar) {
    asm volatile(
        "st.async.weak.shared::cluster.mbarrier::complete_tx::bytes.b32 [%0], %1, [%2];"
        :: "r"(raddr), "r"(v), "r"(rmbar) : "memory");
}
__device__ __forceinline__ void mbar_init(uint mb, uint cnt) {
    asm volatile("mbarrier.init.shared.b64 [%0], %1;" :: "r"(mb), "r"(cnt) : "memory");
}
__device__ __forceinline__ void mbar_expect_tx(uint mb, uint bytes) {
    asm volatile("mbarrier.arrive.expect_tx.shared.b64 _, [%0], %1;"
                 :: "r"(mb), "r"(bytes) : "memory");
}
__device__ __forceinline__ void mbar_wait(uint mb, uint parity) {
    asm volatile(
        "{\n\t.reg .pred P;\n\tW%=:\n\t"
        "mbarrier.try_wait.parity.shared.b64 P, [%0], %1;\n\t"
        "@!P bra W%=;\n\t}"
        :: "r"(mb), "r"(parity) : "memory");
}
#define CLUSTER_SYNC() do { \
    asm volatile("barrier.cluster.arrive.aligned;" ::: "memory"); \
    asm volatile("barrier.cluster.wait.aligned;" ::: "memory"); \
} while (0)
__device__ __forceinline__ void cp_async16(uint daddr, const void* src) {
    asm volatile("cp.async.cg.shared.global [%0], [%1], 16;" :: "r"(daddr), "l"(src));
}
#define CP_COMMIT() asm volatile("cp.async.commit_group;" ::: "memory")
#define CP_WAIT(n)  asm volatile("cp.async.wait_group %0;" :: "n"(n) : "memory")

// ---------------- packing kernels -------------------------------------------------------
__global__ void pack_wh(const float* __restrict__ Wih, const float* __restrict__ Wt) {
    int i = blockIdx.x * blockDim.x + threadIdx.x;
    if (i >= (1024 * Isz) / 8) return;
    int row = i >> 4, q = i & 15;
    const float* s = (row < 768) ? (Wih + (size_t)row * Isz + q * 8)
                                 : (Wt + (size_t)(row - 768) * Isz + q * 8);
    float4 f0 = __ldg((const float4*)s), f1 = __ldg((const float4*)s + 1);
    __half2 h0 = __floats2half2_rn(f0.x, f0.y), h1 = __floats2half2_rn(f0.z, f0.w);
    __half2 h2 = __floats2half2_rn(f1.x, f1.y), h3 = __floats2half2_rn(f1.z, f1.w);
    *(uint4*)(g_wh + (size_t)i * 8) =
        make_uint4(*(uint*)&h0, *(uint*)&h1, *(uint*)&h2, *(uint*)&h3);
}
__global__ void prep_whhf(const float* __restrict__ Whh) {
    int idx = blockIdx.x * blockDim.x + threadIdx.x;
    if (idx >= 96 * 16 * 32) return;
    int lane = idx & 31, kt = (idx >> 5) & 15, nt = idx >> 9;
    int n = nt * 8 + (lane >> 2);
    int k0 = kt * 16 + (lane & 3) * 2;
    const float* s = Whh + (size_t)n * Hsz;
    __half2 lo = __floats2half2_rn(s[k0], s[k0 + 1]);
    __half2 hi = __floats2half2_rn(s[k0 + 8], s[k0 + 9]);
    g_Whf[idx] = make_uint2(*(uint*)&lo, *(uint*)&hi);
}
__global__ void prep_wof(const float* __restrict__ Wo, const float* __restrict__ Wg) {
    int idx = blockIdx.x * blockDim.x + threadIdx.x;
    if (idx >= 16 * 16 * 32) return;
    int lane = idx & 31, kt = (idx >> 5) & 15, nt = idx >> 9;
    int n = nt * 8 + (lane >> 2);
    int k0 = kt * 16 + (lane & 3) * 2;
    const float* s = (n < 64) ? (Wo + (size_t)n * Hsz) : (Wg + (size_t)(n - 64) * Hsz);
    __half2 lo = __floats2half2_rn(s[k0], s[k0 + 1]);
    __half2 hi = __floats2half2_rn(s[k0 + 8], s[k0 + 9]);
    g_Wof[idx] = make_uint2(*(uint*)&lo, *(uint*)&hi);
}

// ---------------- HMMA prepass GEMM v3: M=128 + cp.async double-buffer ------------------
// smem: Xs [128][XSTR] | WsA [128][XSTR] | WsB [128][XSTR]; epilogue reuses Wc.
__global__ void __launch_bounds__(256, 2) gemm_xi(const float* __restrict__ x,
                                                  const float* __restrict__ b_ih,
                                                  const float* __restrict__ bt) {
    extern __shared__ __align__(16) __half sh[];
    __half* Xs  = sh;                        // [128][XSTR]
    __half* WsA = sh + 128 * XSTR;
    __half* WsB = WsA + 128 * XSTR;

    const int tid = threadIdx.x, wid = tid >> 5, lane = tid & 31;
    const int rbase0 = blockIdx.x * 128;
    const int wm = wid & 1, wn = wid >> 1;   // 2x4: 64 rows x 32 cols per warp

    // prologue: async-stage W chunk 0 FIRST (overlaps X conversion below)
#pragma unroll
    for (int i = tid; i < 2048; i += 256) {
        int row = i >> 4, q = i & 15;
        cp_async16(smem_u32(WsA + row * XSTR + q * 8), g_wh + (size_t)i * 8);
    }
    CP_COMMIT();

    { // stage X tile: 128 rows, fp32 -> fp16 fused
#pragma unroll
        for (int i = tid; i < 2048; i += 256) {
            int row = i >> 4, q = i & 15;
            const float4* s = (const float4*)(x + (size_t)(rbase0 + row) * Isz + q * 8);
            float4 f0 = __ldg(s), f1 = __ldg(s + 1);
            __half2 h0 = __floats2half2_rn(f0.x, f0.y), h1 = __floats2half2_rn(f0.z, f0.w);
            __half2 h2 = __floats2half2_rn(f1.x, f1.y), h3 = __floats2half2_rn(f1.z, f1.w);
            *(uint4*)(Xs + row * XSTR + q * 8) =
                make_uint4(*(uint*)&h0, *(uint*)&h1, *(uint*)&h2, *(uint*)&h3);
        }
    }

    for (int chunk = 0; chunk < 8; ++chunk) {
        __half* Wc = (chunk & 1) ? WsB : WsA;
        if (chunk < 7) { // stage next chunk into alternate buffer (Es of chunk-1, drained)
            __half* Wd = (chunk & 1) ? WsA : WsB;
            const char* src = (const char*)(g_wh + (size_t)(chunk + 1) * 128 * Isz);
#pragma unroll
            for (int i = tid; i < 2048; i += 256) {
                int row = i >> 4, q = i & 15;
                cp_async16(smem_u32(Wd + row * XSTR + q * 8), src + (size_t)i * 16);
            }
            CP_COMMIT();
            CP_WAIT(1);
        } else {
            CP_WAIT(0);
        }
        __syncthreads();   // Wc ready (and Xs on chunk 0)

        float acc[4][4][4];
#pragma unroll
        for (int mf = 0; mf < 4; ++mf)
#pragma unroll
            for (int nf = 0; nf < 4; ++nf)
#pragma unroll
                for (int q = 0; q < 4; ++q) acc[mf][nf][q] = 0.0f;

#pragma unroll
        for (int k = 0; k < 8; ++k) {
            uint a[4][4];
#pragma unroll
            for (int mf = 0; mf < 4; ++mf)
                ldm_x4(a[mf], Xs + (wm * 64 + mf * 16 + (lane & 15)) * XSTR
                                 + k * 16 + (lane >> 4) * 8);
            uint bf[4][2];
#pragma unroll
            for (int nf = 0; nf < 4; ++nf)
                ldm_x2(bf[nf], Wc + (wn * 32 + nf * 8 + (lane & 7)) * XSTR
                                  + k * 16 + ((lane >> 3) & 1) * 8);
#pragma unroll
            for (int mf = 0; mf < 4; ++mf)
#pragma unroll
                for (int nf = 0; nf < 4; ++nf)
                    mma16816(acc[mf][nf], a[mf], bf[nf]);
        }
        __syncthreads();   // mma reads of Wc done -> Wc reusable as epilogue buffer

        // epilogue stage 1: bias(+silu), STS transpose into Wc
        const bool do_silu = (chunk >= 6);
#pragma unroll
        for (int nf = 0; nf < 4; ++nf) {
            int cl = wn * 32 + nf * 8 + (lane & 3) * 2;
            int cg = chunk * 128 + cl;
            float bias0, bias1;
            if (!do_silu) { bias0 = __ldg(b_ih + cg); bias1 = __ldg(b_ih + cg + 1); }
            else          { bias0 = __ldg(bt + cg - 768); bias1 = __ldg(bt + cg - 767); }
#pragma unroll
            for (int mf = 0; mf < 4; ++mf) {
#pragma unroll
                for (int h = 0; h < 2; ++h) {
                    int rl = wm * 64 + mf * 16 + (lane >> 2) + h * 8;
                    float v0 = acc[mf][nf][2 * h]     + bias0;
                    float v1 = acc[mf][nf][2 * h + 1] + bias1;
                    if (do_silu) { v0 *= sigmf(v0); v1 *= sigmf(v1); }
                    *(__half2*)(Wc + rl * XSTR + cl) = __floats2half2_rn(v0, v1);
                }
            }
        }
        __syncthreads();   // transpose buffer complete

        // epilogue stage 2: coalesced LDS.128 + STG.128
#pragma unroll
        for (int ii = 0; ii < 8; ++ii) {
            int idx = tid + 256 * ii;
            int row = idx >> 4, q = idx & 15;
            uint4 v = *(uint4*)(Wc + row * XSTR + q * 8);
            *(uint4*)(g_xi + (size_t)(rbase0 + row) * 1024 + chunk * 128 + q * 8) = v;
        }
        __syncthreads();   // Wc drained before it becomes a prefetch target
    }
}

// ---------------- clustered GRU scan: specialized phase D + hidden xi staging -----------
__global__ void __launch_bounds__(STHR, 1) __cluster_dims__(2, 1, 1)
gru_scan(const float* __restrict__ h0, const float* __restrict__ b_hh,
         const float* __restrict__ bo, const float* __restrict__ bg,
         float* __restrict__ out)
{
    extern __shared__ __align__(16) char smraw[];
    const uint smb = smem_u32(smraw);

    const int tid  = threadIdx.x;
    const int w    = tid >> 5, lane = tid & 31;
    const int r    = blockIdx.x & 1;
    const int b0   = (blockIdx.x >> 1) * NBc;
    const uint rsmb = mapa_u32(smb, (uint)(r ^ 1));
    const uint mb   = smb + SM_MBAR;
    const uint rmb  = rsmb + SM_MBAR;

    // ---- phase C thread mapping ----
    const int jp  = tid & 63, j0 = 2 * jp;
    const int grp = tid >> 6;
    const int jg  = 128 * r + j0;

    // ---- phase B warp mapping: 3 n-tiles per warp ----
    const int ntA = 16 * r + w, ntB = 32 + 16 * r + w, ntC = 64 + 16 * r + w;

    // ---- phase D warp mapping: warps 0-7 full-K, warps 8-15 stage xi ----
    const int wl = w & 7;
    const bool isG = (wl >= 4);
    const int ntD = isG ? (8 + 4 * r + (wl & 3)) : (4 * r + (wl & 3));
    const int colD = (isG ? 32 : 0) + (wl & 3) * 8 + 2 * (lane & 3);

    { // init h16[0] and h32 (own j-half)
        int b = tid >> 5, k0 = (tid & 31) * 8;
        const float4* p = (const float4*)(h0 + (size_t)(b0 + b) * Hsz + k0);
        float4 v0 = p[0], v1 = p[1];
        __half2 a0 = __floats2half2_rn(v0.x, v0.y), a1 = __floats2half2_rn(v0.z, v0.w);
        __half2 a2 = __floats2half2_rn(v1.x, v1.y), a3 = __floats2half2_rn(v1.z, v1.w);
        *(uint4*)(smraw + SM_H16(0) + (b * HSTR + k0) * 2) =
            make_uint4(*(uint*)&a0, *(uint*)&a1, *(uint*)&a2, *(uint*)&a3);
        int kq = (tid & 31) * 4;
        if (kq < 128) {
            float4 hv = *(const float4*)(h0 + (size_t)(b0 + b) * Hsz + 128 * r + kq);
            *(float4*)(smraw + SM_H32 + (b * 128 + kq) * 4) = hv;
        }
    }
    if (tid == 0) mbar_init(mb, 1);

    // ---- register-cached invariant fragments ----
    uint2 wfa[16];
#pragma unroll
    for (int kt = 0; kt < 16; ++kt)
        wfa[kt] = __ldg(&g_Whf[(ntA * 16 + kt) * 32 + lane]);
    uint2 wofr[8];   // D fragments kt 0..7 (kt 8..15 via L1-warm ldg)
    if (w < 8) {
#pragma unroll
        for (int ki = 0; ki < 8; ++ki)
            wofr[ki] = __ldg(&g_Wof[(ntD * 16 + ki) * 32 + lane]);
    }

    { // prologue: stage xi(0) with all threads
#pragma unroll
        for (int ii = 0; ii < 2; ++ii) {
            int i = tid + 512 * ii;
            int pair = i >> 4, q = i & 15;
            int b = pair >> 2, seg = pair & 3;
            const uint4* src = (const uint4*)(g_xi +
                ((size_t)(b0 + b) * Tsz) * 1024 + seg * 256 + 128 * r) + q;
            *((uint4*)((__half*)(smraw + SM_XI) + b * 512 + seg * 128) + q) = __ldg(src);
        }
    }

    const float2 hbr2 = *(const float2*)(b_hh + jg);
    const float2 hbz2 = *(const float2*)(b_hh + Hsz + jg);
    const float2 hbn2 = *(const float2*)(b_hh + 2 * Hsz + jg);
    const float boT = __ldg(bo + 32 * r + (tid & 31));
    const float bgT = __ldg(bg + 32 * r + (tid & 31));
    float oacc = 0.0f;

    __syncthreads();
    CLUSTER_SYNC();   // mbarrier init + h16[0] visible cluster-wide

    for (int t = 0; t < Tsz; ++t) {
        const int p = t & 1;
        __half* h16p  = (__half*)(smraw + SM_H16(p));
        __half* h16n  = (__half*)(smraw + SM_H16(p ^ 1));
        __half* v16n  = (__half*)(smraw + SM_V16(p ^ 1));
        __half* xi_s  = (__half*)(smraw + SM_XI);
        float*  hh    = (float*)(smraw + SM_HH);
        float*  h32   = (float*)(smraw + SM_H32);
        float*  redP  = (float*)(smraw + SM_REDP);

        if (tid == 0) mbar_expect_tx(mb, TX_BYTES);

        // ---- Phase B: hh(own 384 cols) = h(16b) @ W_hh^T ----
        {
            const __half* aB = h16p + (lane & 15) * HSTR + (lane >> 4) * 8;
            float acc0[4] = {0.f, 0.f, 0.f, 0.f};
            float acc1[4] = {0.f, 0.f, 0.f, 0.f};
            float acc2[4] = {0.f, 0.f, 0.f, 0.f};
            uint2 fb[2], fc[2];
            fb[0] = __ldg(&g_Whf[(ntB * 16 + 0) * 32 + lane]);
            fc[0] = __ldg(&g_Whf[(ntC * 16 + 0) * 32 + lane]);
            fb[1] = __ldg(&g_Whf[(ntB * 16 + 1) * 32 + lane]);
            fc[1] = __ldg(&g_Whf[(ntC * 16 + 1) * 32 + lane]);
#pragma unroll
            for (int kt = 0; kt < 16; ++kt) {
                const int s = kt & 1;
                uint a[4];
                ldm_x4(a, aB + kt * 16);
                uint2 cb = fb[s], cc2 = fc[s];
                if (kt + 2 < 16) {
                    fb[s] = __ldg(&g_Whf[(ntB * 16 + kt + 2) * 32 + lane]);
                    fc[s] = __ldg(&g_Whf[(ntC * 16 + kt + 2) * 32 + lane]);
                }
                mma16816(acc0, a, (uint*)&wfa[kt]);
                mma16816(acc1, a, (uint*)&cb);
                mma16816(acc2, a, (uint*)&cc2);
            }
            const int bb = lane >> 2, cc = w * 8 + 2 * (lane & 3);
            *(float2*)&hh[bb * 392 + cc]         = make_float2(acc0[0], acc0[1]);
            *(float2*)&hh[(bb + 8) * 392 + cc]   = make_float2(acc0[2], acc0[3]);
            *(float2*)&hh[bb * 392 + 128 + cc]       = make_float2(acc1[0], acc1[1]);
            *(float2*)&hh[(bb + 8) * 392 + 128 + cc] = make_float2(acc1[2], acc1[3]);
            *(float2*)&hh[bb * 392 + 256 + cc]       = make_float2(acc2[0], acc2[1]);
            *(float2*)&hh[(bb + 8) * 392 + 256 + cc] = make_float2(acc2[2], acc2[3]);
        }
        __syncthreads();  // bar1: hh ready (xi was staged in prior D-phase / prologue)

        // ---- Phase C: gates + update for own j-half; remote via st.async ----
#pragma unroll
        for (int q = 0; q < 2; ++q) {
            const int b = grp + 8 * q;
            const __half2* xp = (const __half2*)(xi_s + b * 512 + j0);
            float2 xr = __half22float2(xp[0]);
            float2 xz = __half22float2(xp[64]);
            float2 xn = __half22float2(xp[128]);
            float2 xt = __half22float2(xp[192]);
            const float* hhb = hh + b * 392;
            float2 hr = *(const float2*)(hhb + j0);
            float2 hz = *(const float2*)(hhb + 128 + j0);
            float2 hn = *(const float2*)(hhb + 256 + j0);
            float2 hp = *(const float2*)(h32 + b * 128 + j0);

            float r0 = sigmf(xr.x + hr.x + hbr2.x);
            float r1 = sigmf(xr.y + hr.y + hbr2.y);
            float z0 = sigmf(xz.x + hz.x + hbz2.x);
            float z1 = sigmf(xz.y + hz.y + hbz2.y);
            float n0 = tanhf_(xn.x + r0 * (hn.x + hbn2.x));
            float n1 = tanhf_(xn.y + r1 * (hn.y + hbn2.y));
            float h0n = n0 + z0 * (hp.x - n0);
            float h1n = n1 + z1 * (hp.y - n1);
            *(float2*)(h32 + b * 128 + j0) = make_float2(h0n, h1n);

            __half2 hh2 = __floats2half2_rn(h0n, h1n);
            __half2 vv2 = __floats2half2_rn(h0n + xt.x, h1n + xt.y);
            const uint off_h = (uint)SM_H16(p ^ 1) + (b * HSTR + jg) * 2;
            const uint off_v = (uint)SM_V16(p ^ 1) + (b * HSTR + jg) * 2;
            *(__half2*)(smraw + off_h) = hh2;
            *(__half2*)(smraw + off_v) = vv2;
            st_async_u32(rsmb + off_h, *(uint*)&hh2, rmb);
            st_async_u32(rsmb + off_v, *(uint*)&vv2, rmb);
        }
        __syncthreads();               // local C writes + all xi_s reads complete
        mbar_wait(mb, (uint)(t & 1));  // peer's st.async halves arrived

        // ---- Phase D: warps 0-7 full-K projections; warps 8-15 stage xi(t+1) ----
        if (w < 8) {
            const __half* aD = (isG ? h16n : v16n) + (lane & 15) * HSTR + (lane >> 4) * 8;
            float acc[4] = {0.f, 0.f, 0.f, 0.f};
#pragma unroll
            for (int ki = 0; ki < 8; ++ki) {
                uint a[4];
                ldm_x4(a, aD + ki * 16);
                mma16816(acc, a, (uint*)&wofr[ki]);
            }
#pragma unroll
            for (int ki = 8; ki < 16; ++ki) {
                uint a[4];
                ldm_x4(a, aD + ki * 16);
                uint2 wf = __ldg(&g_Wof[(ntD * 16 + ki) * 32 + lane]);  // L1-warm
                mma16816(acc, a, (uint*)&wf);
            }
            const int bb = lane >> 2;
            *(float2*)&redP[bb * 64 + colD]       = make_float2(acc[0], acc[1]);
            *(float2*)&redP[(bb + 8) * 64 + colD] = make_float2(acc[2], acc[3]);
        } else if (t + 1 < Tsz) {
            // stage xi(t+1): 16 KB with 256 threads (xi_s dead after phase C)
            const int tt = tid & 255;
#pragma unroll
            for (int ii = 0; ii < 4; ++ii) {
                int i = tt + 256 * ii;
                int pair = i >> 4, q = i & 15;
                int b = pair >> 2, seg = pair & 3;
                const uint4* src = (const uint4*)(g_xi +
                    ((size_t)(b0 + b) * Tsz + t + 1) * 1024 + seg * 256 + 128 * r) + q;
                *((uint4*)(xi_s + b * 512 + seg * 128) + q) = __ldg(src);
            }
        }
        __syncthreads();  // bar3: redP + staged xi ready

        { // finalize: thread owns (b = tid>>5, c = tid&31)
            const int b = tid >> 5, c = tid & 31;
            float pr = redP[b * 64 + c] + boT;
            float gt = redP[b * 64 + 32 + c] + bgT;
            oacc += pr * sigmf(gt);
        }
    }

    { // output: CTA r writes cols [32r, 32r+32)
        const int b = tid >> 5, c = tid & 31;
        out[(size_t)(b0 + b) * Osz + 32 * r + c] = oacc * (1.0f / (float)Tsz);
    }
    CLUSTER_SYNC();   // keep smem alive until peer fully drained
}

// ---------------- launch -----------------------------------------------------------------
extern "C" void kernel_launch(void* const* d_in, const int* in_sizes, int n_in,
                              void* d_out, int out_size) {
    const float* x    = (const float*)d_in[0];
    const float* h0   = (const float*)d_in[1];
    const float* W_ih = (const float*)d_in[2];
    const float* b_ih = (const float*)d_in[3];
    const float* W_hh = (const float*)d_in[4];
    const float* b_hh = (const float*)d_in[5];
    const float* Wt   = (const float*)d_in[6];
    const float* bt   = (const float*)d_in[7];
    const float* Wo   = (const float*)d_in[8];
    const float* bo   = (const float*)d_in[9];
    const float* Wg   = (const float*)d_in[10];
    const float* bg   = (const float*)d_in[11];
    float* out = (float*)d_out;

    const int GEMM_SMEM = 3 * 128 * XSTR * 2;   // 104448
    cudaFuncSetAttribute(gemm_xi, cudaFuncAttributeMaxDynamicSharedMemorySize, GEMM_SMEM);
    cudaFuncSetAttribute(gru_scan, cudaFuncAttributeMaxDynamicSharedMemorySize, SM_TOTAL);

    pack_wh<<<(1024 * Isz / 8 + 255) / 256, 256>>>(W_ih, Wt);
    prep_whhf<<<(96 * 16 * 32 + 255) / 256, 256>>>(W_hh);
    prep_wof<<<(16 * 16 * 32 + 255) / 256, 256>>>(Wo, Wg);
    gemm_xi<<<(Bsz * Tsz) / 128, 256, GEMM_SMEM>>>(x, b_ih, bt);
    gru_scan<<<NCTA, STHR, SM_TOTAL>>>(h0, b_hh, bo, bg, out);
}

// round 16
// speedup vs baseline: 1.9549x; 1.0544x over previous
#include <cuda_runtime.h>
#include <cuda_fp16.h>

typedef unsigned long long ull;
typedef unsigned int uint;

#define Bsz 1024
#define Tsz 512
#define Isz 128
#define Hsz 256
#define Osz 64
#define NBc 16      // batches per cluster
#define NCTA 128    // 64 clusters x 2
#define STHR 512
#define XSTR 136    // gemm smem row stride (halves)
#define HSTR 264    // h16/v16 row stride (halves): conflict-free ldmatrix

// ---------------- device scratch -----------------------------------------------------
// g_xi layout [b][t][1024]: 0..255 xr, 256..511 xz, 512..767 xn (+b_ih), 768..1023 silu
__device__ __half g_xi[(size_t)Bsz * Tsz * 1024];    // 1.07 GB
__device__ __half g_wh[(size_t)1024 * Isz];          // [W_ih;Wt] fp16 for prepass
__device__ uint2  g_Whf[96 * 16 * 32];               // W_hh fragment-major fp16 (393 KB)
__device__ uint2  g_Wof[16 * 16 * 32];               // [Wo;Wg] fragment-major fp16 (64 KB)

// ---------------- scan smem layout (bytes) --------------------------------------------
#define SM_H16(p)  ((p) * 8448)            // [2][16][HSTR] f16
#define SM_V16(p)  (16896 + (p) * 8448)    // [2][16][HSTR] f16
#define SM_H32     33792                   // [16][128] f32 (own j-half)
#define SM_HH      41984                   // [16][392] f32 (own 384 cols + pad)
#define SM_XI      67072                   // [16][512] f16 (own 4x128 cols)
#define SM_REDP    83456                   // [16][64] f32
#define SM_MBAR    87552                   // mbarrier (8 B)
#define SM_TOTAL   87568
#define TX_BYTES   8192u                   // 512 thr x 4 st.async x 4 B

// ---------------- helpers --------------------------------------------------------------
__device__ __forceinline__ float sigmf(float x) { return 1.0f / (1.0f + __expf(-x)); }
__device__ __forceinline__ float tanhf_(float x) {
    float a = fabsf(x);
    float e = __expf(-2.0f * a);
    return copysignf((1.0f - e) / (1.0f + e), x);
}
__device__ __forceinline__ uint smem_u32(const void* p) {
    uint a;
    asm("{ .reg .u64 t; cvta.to.shared.u64 t, %1; cvt.u32.u64 %0, t; }" : "=r"(a) : "l"(p));
    return a;
}
__device__ __forceinline__ void ldm_x4(uint* a, const __half* p) {
    uint addr = smem_u32(p);
    asm volatile("ldmatrix.sync.aligned.m8n8.x4.shared.b16 {%0,%1,%2,%3}, [%4];"
                 : "=r"(a[0]), "=r"(a[1]), "=r"(a[2]), "=r"(a[3]) : "r"(addr));
}
__device__ __forceinline__ void ldm_x2(uint* b, const __half* p) {
    uint addr = smem_u32(p);
    asm volatile("ldmatrix.sync.aligned.m8n8.x2.shared.b16 {%0,%1}, [%2];"
                 : "=r"(b[0]), "=r"(b[1]) : "r"(addr));
}
__device__ __forceinline__ void mma16816(float* d, const uint* a, const uint* b) {
    asm volatile(
        "mma.sync.aligned.m16n8k16.row.col.f32.f16.f16.f32 "
        "{%0,%1,%2,%3}, {%4,%5,%6,%7}, {%8,%9}, {%0,%1,%2,%3};"
        : "+f"(d[0]), "+f"(d[1]), "+f"(d[2]), "+f"(d[3])
        : "r"(a[0]), "r"(a[1]), "r"(a[2]), "r"(a[3]), "r"(b[0]), "r"(b[1]));
}
__device__ __forceinline__ uint mapa_u32(uint addr, uint rank) {
    uint r;
    asm("mapa.shared::cluster.u32 %0, %1, %2;" : "=r"(r) : "r"(addr), "r"(rank));
    return r;
}
__device__ __forceinline__ void st_async_u32(uint raddr, uint v, uint rmbar) {
    asm volatile(
        "st.async.weak.shared::cluster.mbarrier::complete_tx::bytes.b32 [%0], %1, [%2];"
        :: "r"(raddr), "r"(v), "r"(rmbar) : "memory");
}
__device__ __forceinline__ void mbar_init(uint mb, uint cnt) {
    asm volatile("mbarrier.init.shared.b64 [%0], %1;" :: "r"(mb), "r"(cnt) : "memory");
}
__device__ __forceinline__ void mbar_expect_tx(uint mb, uint bytes) {
    asm volatile("mbarrier.arrive.expect_tx.shared.b64 _, [%0], %1;"
                 :: "r"(mb), "r"(bytes) : "memory");
}
__device__ __forceinline__ void mbar_wait(uint mb, uint parity) {
    asm volatile(
        "{\n\t.reg .pred P;\n\tW%=:\n\t"
        "mbarrier.try_wait.parity.shared.b64 P, [%0], %1;\n\t"
        "@!P bra W%=;\n\t}"
        :: "r"(mb), "r"(parity) : "memory");
}
#define CLUSTER_SYNC() do { \
    asm volatile("barrier.cluster.arrive.aligned;" ::: "memory"); \
    asm volatile("barrier.cluster.wait.aligned;" ::: "memory"); \
} while (0)
__device__ __forceinline__ void cp_async16(uint daddr, const void* src) {
    asm volatile("cp.async.cg.shared.global [%0], [%1], 16;" :: "r"(daddr), "l"(src));
}
#define CP_COMMIT() asm volatile("cp.async.commit_group;" ::: "memory")
#define CP_WAIT(n)  asm volatile("cp.async.wait_group %0;" :: "n"(n) : "memory")

// ---------------- packing kernels -------------------------------------------------------
__global__ void pack_wh(const float* __restrict__ Wih, const float* __restrict__ Wt) {
    int i = blockIdx.x * blockDim.x + threadIdx.x;
    if (i >= (1024 * Isz) / 8) return;
    int row = i >> 4, q = i & 15;
    const float* s = (row < 768) ? (Wih + (size_t)row * Isz + q * 8)
                                 : (Wt + (size_t)(row - 768) * Isz + q * 8);
    float4 f0 = __ldg((const float4*)s), f1 = __ldg((const float4*)s + 1);
    __half2 h0 = __floats2half2_rn(f0.x, f0.y), h1 = __floats2half2_rn(f0.z, f0.w);
    __half2 h2 = __floats2half2_rn(f1.x, f1.y), h3 = __floats2half2_rn(f1.z, f1.w);
    *(uint4*)(g_wh + (size_t)i * 8) =
        make_uint4(*(uint*)&h0, *(uint*)&h1, *(uint*)&h2, *(uint*)&h3);
}
__global__ void prep_whhf(const float* __restrict__ Whh) {
    int idx = blockIdx.x * blockDim.x + threadIdx.x;
    if (idx >= 96 * 16 * 32) return;
    int lane = idx & 31, kt = (idx >> 5) & 15, nt = idx >> 9;
    int n = nt * 8 + (lane >> 2);
    int k0 = kt * 16 + (lane & 3) * 2;
    const float* s = Whh + (size_t)n * Hsz;
    __half2 lo = __floats2half2_rn(s[k0], s[k0 + 1]);
    __half2 hi = __floats2half2_rn(s[k0 + 8], s[k0 + 9]);
    g_Whf[idx] = make_uint2(*(uint*)&lo, *(uint*)&hi);
}
__global__ void prep_wof(const float* __restrict__ Wo, const float* __restrict__ Wg) {
    int idx = blockIdx.x * blockDim.x + threadIdx.x;
    if (idx >= 16 * 16 * 32) return;
    int lane = idx & 31, kt = (idx >> 5) & 15, nt = idx >> 9;
    int n = nt * 8 + (lane >> 2);
    int k0 = kt * 16 + (lane & 3) * 2;
    const float* s = (n < 64) ? (Wo + (size_t)n * Hsz) : (Wg + (size_t)(n - 64) * Hsz);
    __half2 lo = __floats2half2_rn(s[k0], s[k0 + 1]);
    __half2 hi = __floats2half2_rn(s[k0 + 8], s[k0 + 9]);
    g_Wof[idx] = make_uint2(*(uint*)&lo, *(uint*)&hi);
}

// ---------------- HMMA prepass GEMM v3 (unchanged from R15) -----------------------------
__global__ void __launch_bounds__(256, 2) gemm_xi(const float* __restrict__ x,
                                                  const float* __restrict__ b_ih,
                                                  const float* __restrict__ bt) {
    extern __shared__ __align__(16) __half sh[];
    __half* Xs  = sh;                        // [128][XSTR]
    __half* WsA = sh + 128 * XSTR;
    __half* WsB = WsA + 128 * XSTR;

    const int tid = threadIdx.x, wid = tid >> 5, lane = tid & 31;
    const int rbase0 = blockIdx.x * 128;
    const int wm = wid & 1, wn = wid >> 1;

#pragma unroll
    for (int i = tid; i < 2048; i += 256) {
        int row = i >> 4, q = i & 15;
        cp_async16(smem_u32(WsA + row * XSTR + q * 8), g_wh + (size_t)i * 8);
    }
    CP_COMMIT();

#pragma unroll
    for (int i = tid; i < 2048; i += 256) {
        int row = i >> 4, q = i & 15;
        const float4* s = (const float4*)(x + (size_t)(rbase0 + row) * Isz + q * 8);
        float4 f0 = __ldg(s), f1 = __ldg(s + 1);
        __half2 h0 = __floats2half2_rn(f0.x, f0.y), h1 = __floats2half2_rn(f0.z, f0.w);
        __half2 h2 = __floats2half2_rn(f1.x, f1.y), h3 = __floats2half2_rn(f1.z, f1.w);
        *(uint4*)(Xs + row * XSTR + q * 8) =
            make_uint4(*(uint*)&h0, *(uint*)&h1, *(uint*)&h2, *(uint*)&h3);
    }

    for (int chunk = 0; chunk < 8; ++chunk) {
        __half* Wc = (chunk & 1) ? WsB : WsA;
        if (chunk < 7) {
            __half* Wd = (chunk & 1) ? WsA : WsB;
            const char* src = (const char*)(g_wh + (size_t)(chunk + 1) * 128 * Isz);
#pragma unroll
            for (int i = tid; i < 2048; i += 256) {
                int row = i >> 4, q = i & 15;
                cp_async16(smem_u32(Wd + row * XSTR + q * 8), src + (size_t)i * 16);
            }
            CP_COMMIT();
            CP_WAIT(1);
        } else {
            CP_WAIT(0);
        }
        __syncthreads();

        float acc[4][4][4];
#pragma unroll
        for (int mf = 0; mf < 4; ++mf)
#pragma unroll
            for (int nf = 0; nf < 4; ++nf)
#pragma unroll
                for (int q = 0; q < 4; ++q) acc[mf][nf][q] = 0.0f;

#pragma unroll
        for (int k = 0; k < 8; ++k) {
            uint a[4][4];
#pragma unroll
            for (int mf = 0; mf < 4; ++mf)
                ldm_x4(a[mf], Xs + (wm * 64 + mf * 16 + (lane & 15)) * XSTR
                                 + k * 16 + (lane >> 4) * 8);
            uint bf[4][2];
#pragma unroll
            for (int nf = 0; nf < 4; ++nf)
                ldm_x2(bf[nf], Wc + (wn * 32 + nf * 8 + (lane & 7)) * XSTR
                                  + k * 16 + ((lane >> 3) & 1) * 8);
#pragma unroll
            for (int mf = 0; mf < 4; ++mf)
#pragma unroll
                for (int nf = 0; nf < 4; ++nf)
                    mma16816(acc[mf][nf], a[mf], bf[nf]);
        }
        __syncthreads();

        const bool do_silu = (chunk >= 6);
#pragma unroll
        for (int nf = 0; nf < 4; ++nf) {
            int cl = wn * 32 + nf * 8 + (lane & 3) * 2;
            int cg = chunk * 128 + cl;
            float bias0, bias1;
            if (!do_silu) { bias0 = __ldg(b_ih + cg); bias1 = __ldg(b_ih + cg + 1); }
            else          { bias0 = __ldg(bt + cg - 768); bias1 = __ldg(bt + cg - 767); }
#pragma unroll
            for (int mf = 0; mf < 4; ++mf) {
#pragma unroll
                for (int h = 0; h < 2; ++h) {
                    int rl = wm * 64 + mf * 16 + (lane >> 2) + h * 8;
                    float v0 = acc[mf][nf][2 * h]     + bias0;
                    float v1 = acc[mf][nf][2 * h + 1] + bias1;
                    if (do_silu) { v0 *= sigmf(v0); v1 *= sigmf(v1); }
                    *(__half2*)(Wc + rl * XSTR + cl) = __floats2half2_rn(v0, v1);
                }
            }
        }
        __syncthreads();

#pragma unroll
        for (int ii = 0; ii < 8; ++ii) {
            int idx = tid + 256 * ii;
            int row = idx >> 4, q = idx & 15;
            uint4 v = *(uint4*)(Wc + row * XSTR + q * 8);
            *(uint4*)(g_xi + (size_t)(rbase0 + row) * 1024 + chunk * 128 + q * 8) = v;
        }
        __syncthreads();
    }
}

// ---------------- scan phase B (inlined twice: prologue + merged BD) ---------------------
__device__ __forceinline__ void phaseB(
    const __half* h16buf, float* hh, const uint2* wfa,
    int ntB, int ntC, int w, int lane)
{
    const __half* aB = h16buf + (lane & 15) * HSTR + (lane >> 4) * 8;
    float acc0[4] = {0.f, 0.f, 0.f, 0.f};
    float acc1[4] = {0.f, 0.f, 0.f, 0.f};
    float acc2[4] = {0.f, 0.f, 0.f, 0.f};
    uint2 fb[2], fc[2];
    fb[0] = __ldg(&g_Whf[(ntB * 16 + 0) * 32 + lane]);
    fc[0] = __ldg(&g_Whf[(ntC * 16 + 0) * 32 + lane]);
    fb[1] = __ldg(&g_Whf[(ntB * 16 + 1) * 32 + lane]);
    fc[1] = __ldg(&g_Whf[(ntC * 16 + 1) * 32 + lane]);
#pragma unroll
    for (int kt = 0; kt < 16; ++kt) {
        const int s = kt & 1;
        uint a[4];
        ldm_x4(a, aB + kt * 16);
        uint2 cb = fb[s], cc2 = fc[s];
        if (kt + 2 < 16) {
            fb[s] = __ldg(&g_Whf[(ntB * 16 + kt + 2) * 32 + lane]);
            fc[s] = __ldg(&g_Whf[(ntC * 16 + kt + 2) * 32 + lane]);
        }
        mma16816(acc0, a, (uint*)&wfa[kt]);
        mma16816(acc1, a, (uint*)&cb);
        mma16816(acc2, a, (uint*)&cc2);
    }
    const int bb = lane >> 2, cc = w * 8 + 2 * (lane & 3);
    *(float2*)&hh[bb * 392 + cc]             = make_float2(acc0[0], acc0[1]);
    *(float2*)&hh[(bb + 8) * 392 + cc]       = make_float2(acc0[2], acc0[3]);
    *(float2*)&hh[bb * 392 + 128 + cc]       = make_float2(acc1[0], acc1[1]);
    *(float2*)&hh[(bb + 8) * 392 + 128 + cc] = make_float2(acc1[2], acc1[3]);
    *(float2*)&hh[bb * 392 + 256 + cc]       = make_float2(acc2[0], acc2[1]);
    *(float2*)&hh[(bb + 8) * 392 + 256 + cc] = make_float2(acc2[2], acc2[3]);
}

// ---------------- clustered GRU scan: merged BD phase (D(t) || B(t+1)) -------------------
__global__ void __launch_bounds__(STHR, 1) __cluster_dims__(2, 1, 1)
gru_scan(const float* __restrict__ h0, const float* __restrict__ b_hh,
         const float* __restrict__ bo, const float* __restrict__ bg,
         float* __restrict__ out)
{
    extern __shared__ __align__(16) char smraw[];
    const uint smb = smem_u32(smraw);

    const int tid  = threadIdx.x;
    const int w    = tid >> 5, lane = tid & 31;
    const int r    = blockIdx.x & 1;
    const int b0   = (blockIdx.x >> 1) * NBc;
    const uint rsmb = mapa_u32(smb, (uint)(r ^ 1));
    const uint mb   = smb + SM_MBAR;
    const uint rmb  = rsmb + SM_MBAR;

    const int jp  = tid & 63, j0 = 2 * jp;
    const int grp = tid >> 6;
    const int jg  = 128 * r + j0;

    const int ntA = 16 * r + w, ntB = 32 + 16 * r + w, ntC = 64 + 16 * r + w;

    const int wl = w & 7;
    const bool isG = (wl >= 4);
    const int ntD = isG ? (8 + 4 * r + (wl & 3)) : (4 * r + (wl & 3));
    const int colD = (isG ? 32 : 0) + (wl & 3) * 8 + 2 * (lane & 3);

    { // init h16[0] and h32 (own j-half)
        int b = tid >> 5, k0 = (tid & 31) * 8;
        const float4* p = (const float4*)(h0 + (size_t)(b0 + b) * Hsz + k0);
        float4 v0 = p[0], v1 = p[1];
        __half2 a0 = __floats2half2_rn(v0.x, v0.y), a1 = __floats2half2_rn(v0.z, v0.w);
        __half2 a2 = __floats2half2_rn(v1.x, v1.y), a3 = __floats2half2_rn(v1.z, v1.w);
        *(uint4*)(smraw + SM_H16(0) + (b * HSTR + k0) * 2) =
            make_uint4(*(uint*)&a0, *(uint*)&a1, *(uint*)&a2, *(uint*)&a3);
        int kq = (tid & 31) * 4;
        if (kq < 128) {
            float4 hv = *(const float4*)(h0 + (size_t)(b0 + b) * Hsz + 128 * r + kq);
            *(float4*)(smraw + SM_H32 + (b * 128 + kq) * 4) = hv;
        }
    }
    if (tid == 0) mbar_init(mb, 1);

    // register-cached invariant fragments
    uint2 wfa[16];
#pragma unroll
    for (int kt = 0; kt < 16; ++kt)
        wfa[kt] = __ldg(&g_Whf[(ntA * 16 + kt) * 32 + lane]);
    uint2 wofr[8];
    if (w < 8) {
#pragma unroll
        for (int ki = 0; ki < 8; ++ki)
            wofr[ki] = __ldg(&g_Wof[(ntD * 16 + ki) * 32 + lane]);
    }

    { // prologue: stage xi(0)
#pragma unroll
        for (int ii = 0; ii < 2; ++ii) {
            int i = tid + 512 * ii;
            int pair = i >> 4, q = i & 15;
            int b = pair >> 2, seg = pair & 3;
            const uint4* src = (const uint4*)(g_xi +
                ((size_t)(b0 + b) * Tsz) * 1024 + seg * 256 + 128 * r) + q;
            *((uint4*)((__half*)(smraw + SM_XI) + b * 512 + seg * 128) + q) = __ldg(src);
        }
    }

    const float2 hbr2 = *(const float2*)(b_hh + jg);
    const float2 hbz2 = *(const float2*)(b_hh + Hsz + jg);
    const float2 hbn2 = *(const float2*)(b_hh + 2 * Hsz + jg);
    const float boT = __ldg(bo + 32 * r + (tid & 31));
    const float bgT = __ldg(bg + 32 * r + (tid & 31));
    float oacc = 0.0f;

    __syncthreads();
    CLUSTER_SYNC();   // mbarrier init + h16[0] visible cluster-wide

    // prologue: B(0) -> hh
    phaseB((const __half*)(smraw + SM_H16(0)), (float*)(smraw + SM_HH),
           wfa, ntB, ntC, w, lane);
    __syncthreads();  // hh(0) ready

    for (int t = 0; t < Tsz; ++t) {
        const int p = t & 1;
        __half* h16n  = (__half*)(smraw + SM_H16(p ^ 1));
        __half* v16n  = (__half*)(smraw + SM_V16(p ^ 1));
        __half* xi_s  = (__half*)(smraw + SM_XI);
        float*  hh    = (float*)(smraw + SM_HH);
        float*  h32   = (float*)(smraw + SM_H32);
        float*  redP  = (float*)(smraw + SM_REDP);

        if (tid == 0) mbar_expect_tx(mb, TX_BYTES);

        // ---- Phase C: gates + update for own j-half; remote via st.async ----
#pragma unroll
        for (int q = 0; q < 2; ++q) {
            const int b = grp + 8 * q;
            const __half2* xp = (const __half2*)(xi_s + b * 512 + j0);
            float2 xr = __half22float2(xp[0]);
            float2 xz = __half22float2(xp[64]);
            float2 xn = __half22float2(xp[128]);
            float2 xt = __half22float2(xp[192]);
            const float* hhb = hh + b * 392;
            float2 hr = *(const float2*)(hhb + j0);
            float2 hz = *(const float2*)(hhb + 128 + j0);
            float2 hn = *(const float2*)(hhb + 256 + j0);
            float2 hp = *(const float2*)(h32 + b * 128 + j0);

            float r0 = sigmf(xr.x + hr.x + hbr2.x);
            float r1 = sigmf(xr.y + hr.y + hbr2.y);
            float z0 = sigmf(xz.x + hz.x + hbz2.x);
            float z1 = sigmf(xz.y + hz.y + hbz2.y);
            float n0 = tanhf_(xn.x + r0 * (hn.x + hbn2.x));
            float n1 = tanhf_(xn.y + r1 * (hn.y + hbn2.y));
            float h0n = n0 + z0 * (hp.x - n0);
            float h1n = n1 + z1 * (hp.y - n1);
            *(float2*)(h32 + b * 128 + j0) = make_float2(h0n, h1n);

            __half2 hh2 = __floats2half2_rn(h0n, h1n);
            __half2 vv2 = __floats2half2_rn(h0n + xt.x, h1n + xt.y);
            const uint off_h = (uint)SM_H16(p ^ 1) + (b * HSTR + jg) * 2;
            const uint off_v = (uint)SM_V16(p ^ 1) + (b * HSTR + jg) * 2;
            *(__half2*)(smraw + off_h) = hh2;
            *(__half2*)(smraw + off_v) = vv2;
            st_async_u32(rsmb + off_h, *(uint*)&hh2, rmb);
            st_async_u32(rsmb + off_v, *(uint*)&vv2, rmb);
        }
        __syncthreads();               // local C writes + hh/xi consumption complete
        mbar_wait(mb, (uint)(t & 1));  // peer's st.async halves arrived

        // ---- Merged BD: D(t) (warps 0-7) / xi(t+1) staging (warps 8-15), then B(t+1) ----
        if (w < 8) {
            const __half* aD = (isG ? h16n : v16n) + (lane & 15) * HSTR + (lane >> 4) * 8;
            float acc[4] = {0.f, 0.f, 0.f, 0.f};
#pragma unroll
            for (int ki = 0; ki < 8; ++ki) {
                uint a[4];
                ldm_x4(a, aD + ki * 16);
                mma16816(acc, a, (uint*)&wofr[ki]);
            }
#pragma unroll
            for (int ki = 8; ki < 16; ++ki) {
                uint a[4];
                ldm_x4(a, aD + ki * 16);
                uint2 wf = __ldg(&g_Wof[(ntD * 16 + ki) * 32 + lane]);  // L1-warm
                mma16816(acc, a, (uint*)&wf);
            }
            const int bb = lane >> 2;
            *(float2*)&redP[bb * 64 + colD]       = make_float2(acc[0], acc[1]);
            *(float2*)&redP[(bb + 8) * 64 + colD] = make_float2(acc[2], acc[3]);
        } else if (t + 1 < Tsz) {
            const int tt = tid & 255;
#pragma unroll
            for (int ii = 0; ii < 4; ++ii) {
                int i = tt + 256 * ii;
                int pair = i >> 4, q = i & 15;
                int b = pair >> 2, seg = pair & 3;
                const uint4* src = (const uint4*)(g_xi +
                    ((size_t)(b0 + b) * Tsz + t + 1) * 1024 + seg * 256 + 128 * r) + q;
                *((uint4*)(xi_s + b * 512 + seg * 128) + q) = __ldg(src);
            }
        }
        // B(t+1): reads h16n (state after C(t)); writes hh for C(t+1)
        if (t + 1 < Tsz)
            phaseB(h16n, hh, wfa, ntB, ntC, w, lane);
        __syncthreads();  // redP + hh(t+1) + xi(t+1) ready

        { // finalize(t)
            const int b = tid >> 5, c = tid & 31;
            float pr = redP[b * 64 + c] + boT;
            float gt = redP[b * 64 + 32 + c] + bgT;
            oacc += pr * sigmf(gt);
        }
    }

    { // output: CTA r writes cols [32r, 32r+32)
        const int b = tid >> 5, c = tid & 31;
        out[(size_t)(b0 + b) * Osz + 32 * r + c] = oacc * (1.0f / (float)Tsz);
    }
    CLUSTER_SYNC();   // keep smem alive until peer fully drained
}

// ---------------- launch -----------------------------------------------------------------
extern "C" void kernel_launch(void* const* d_in, const int* in_sizes, int n_in,
                              void* d_out, int out_size) {
    const float* x    = (const float*)d_in[0];
    const float* h0   = (const float*)d_in[1];
    const float* W_ih = (const float*)d_in[2];
    const float* b_ih = (const float*)d_in[3];
    const float* W_hh = (const float*)d_in[4];
    const float* b_hh = (const float*)d_in[5];
    const float* Wt   = (const float*)d_in[6];
    const float* bt   = (const float*)d_in[7];
    const float* Wo   = (const float*)d_in[8];
    const float* bo   = (const float*)d_in[9];
    const float* Wg   = (const float*)d_in[10];
    const float* bg   = (const float*)d_in[11];
    float* out = (float*)d_out;

    const int GEMM_SMEM = 3 * 128 * XSTR * 2;   // 104448
    cudaFuncSetAttribute(gemm_xi, cudaFuncAttributeMaxDynamicSharedMemorySize, GEMM_SMEM);
    cudaFuncSetAttribute(gru_scan, cudaFuncAttributeMaxDynamicSharedMemorySize, SM_TOTAL);

    pack_wh<<<(1024 * Isz / 8 + 255) / 256, 256>>>(W_ih, Wt);
    prep_whhf<<<(96 * 16 * 32 + 255) / 256, 256>>>(W_hh);
    prep_wof<<<(16 * 16 * 32 + 255) / 256, 256>>>(Wo, Wg);
    gemm_xi<<<(Bsz * Tsz) / 128, 256, GEMM_SMEM>>>(x, b_ih, bt);
    gru_scan<<<NCTA, STHR, SM_TOTAL>>>(h0, b_hh, bo, bg, out);
}

// round 17
// speedup vs baseline: 2.3588x; 1.2066x over previous
#include <cuda_runtime.h>
#include <cuda_fp16.h>

typedef unsigned long long ull;
typedef unsigned int uint;

#define Bsz 1024
#define Tsz 512
#define Isz 128
#define Hsz 256
#define Osz 64
#define NBc 16      // batches per cluster
#define NCTA 128    // 64 clusters x 2
#define STHR 512
#define XSTR 136    // gemm smem row stride (halves)
#define HSTR 264    // h16/v16 row stride (halves): conflict-free ldmatrix

// ---------------- device scratch -----------------------------------------------------
// g_xi layout [b][t][1024]: 0..255 xr, 256..511 xz, 512..767 xn (+b_ih), 768..1023 silu
__device__ __half g_xi[(size_t)Bsz * Tsz * 1024];    // 1.07 GB
__device__ __half g_wh[(size_t)1024 * Isz];          // [W_ih;Wt] fp16 for prepass
__device__ uint2  g_Whf[96 * 16 * 32];               // W_hh fragment-major fp16 (393 KB)
__device__ uint2  g_Wof[16 * 16 * 32];               // [Wo;Wg] fragment-major fp16 (64 KB)

// ---------------- scan smem layout (bytes) --------------------------------------------
#define SM_H16(p)  ((p) * 8448)            // [2][16][HSTR] f16
#define SM_V16(p)  (16896 + (p) * 8448)    // [2][16][HSTR] f16
#define SM_H32     33792                   // [16][128] f32 (own j-half)
#define SM_HH      41984                   // [16][392] f32 (own 384 cols + pad)
#define SM_XI      67072                   // [16][512] f16 (own 4x128 cols)
#define SM_REDP    83456                   // [16][64] f32
#define SM_MBAR    87552                   // mbarrier (8 B)
#define SM_TOTAL   87568
#define TX_BYTES   8192u                   // 512 thr x 4 st.async x 4 B

// ---------------- helpers --------------------------------------------------------------
__device__ __forceinline__ float sigmf(float x) { return 1.0f / (1.0f + __expf(-x)); }
__device__ __forceinline__ float tanh_ap(float x) {
    float r;
    asm("tanh.approx.f32 %0, %1;" : "=f"(r) : "f"(x));
    return r;
}
__device__ __forceinline__ float sig_ap(float x) {
    return fmaf(0.5f, tanh_ap(0.5f * x), 0.5f);
}
__device__ __forceinline__ uint smem_u32(const void* p) {
    uint a;
    asm("{ .reg .u64 t; cvta.to.shared.u64 t, %1; cvt.u32.u64 %0, t; }" : "=r"(a) : "l"(p));
    return a;
}
__device__ __forceinline__ void ldm_x4(uint* a, const __half* p) {
    uint addr = smem_u32(p);
    asm volatile("ldmatrix.sync.aligned.m8n8.x4.shared.b16 {%0,%1,%2,%3}, [%4];"
                 : "=r"(a[0]), "=r"(a[1]), "=r"(a[2]), "=r"(a[3]) : "r"(addr));
}
__device__ __forceinline__ void ldm_x2(uint* b, const __half* p) {
    uint addr = smem_u32(p);
    asm volatile("ldmatrix.sync.aligned.m8n8.x2.shared.b16 {%0,%1}, [%2];"
                 : "=r"(b[0]), "=r"(b[1]) : "r"(addr));
}
__device__ __forceinline__ void mma16816(float* d, const uint* a, const uint* b) {
    asm volatile(
        "mma.sync.aligned.m16n8k16.row.col.f32.f16.f16.f32 "
        "{%0,%1,%2,%3}, {%4,%5,%6,%7}, {%8,%9}, {%0,%1,%2,%3};"
        : "+f"(d[0]), "+f"(d[1]), "+f"(d[2]), "+f"(d[3])
        : "r"(a[0]), "r"(a[1]), "r"(a[2]), "r"(a[3]), "r"(b[0]), "r"(b[1]));
}
__device__ __forceinline__ uint mapa_u32(uint addr, uint rank) {
    uint r;
    asm("mapa.shared::cluster.u32 %0, %1, %2;" : "=r"(r) : "r"(addr), "r"(rank));
    return r;
}
__device__ __forceinline__ void st_async_u32(uint raddr, uint v, uint rmbar) {
    asm volatile(
        "st.async.weak.shared::cluster.mbarrier::complete_tx::bytes.b32 [%0], %1, [%2];"
        :: "r"(raddr), "r"(v), "r"(rmbar) : "memory");
}
__device__ __forceinline__ void mbar_init(uint mb, uint cnt) {
    asm volatile("mbarrier.init.shared.b64 [%0], %1;" :: "r"(mb), "r"(cnt) : "memory");
}
__device__ __forceinline__ void mbar_expect_tx(uint mb, uint bytes) {
    asm volatile("mbarrier.arrive.expect_tx.shared.b64 _, [%0], %1;"
                 :: "r"(mb), "r"(bytes) : "memory");
}
__device__ __forceinline__ void mbar_wait(uint mb, uint parity) {
    asm volatile(
        "{\n\t.reg .pred P;\n\tW%=:\n\t"
        "mbarrier.try_wait.parity.shared.b64 P, [%0], %1;\n\t"
        "@!P bra W%=;\n\t}"
        :: "r"(mb), "r"(parity) : "memory");
}
#define CLUSTER_SYNC() do { \
    asm volatile("barrier.cluster.arrive.aligned;" ::: "memory"); \
    asm volatile("barrier.cluster.wait.aligned;" ::: "memory"); \
} while (0)
__device__ __forceinline__ void cp_async16(uint daddr, const void* src) {
    asm volatile("cp.async.cg.shared.global [%0], [%1], 16;" :: "r"(daddr), "l"(src));
}
#define CP_COMMIT() asm volatile("cp.async.commit_group;" ::: "memory")
#define CP_WAIT(n)  asm volatile("cp.async.wait_group %0;" :: "n"(n) : "memory")

// ---------------- packing kernels -------------------------------------------------------
__global__ void pack_wh(const float* __restrict__ Wih, const float* __restrict__ Wt) {
    int i = blockIdx.x * blockDim.x + threadIdx.x;
    if (i >= (1024 * Isz) / 8) return;
    int row = i >> 4, q = i & 15;
    const float* s = (row < 768) ? (Wih + (size_t)row * Isz + q * 8)
                                 : (Wt + (size_t)(row - 768) * Isz + q * 8);
    float4 f0 = __ldg((const float4*)s), f1 = __ldg((const float4*)s + 1);
    __half2 h0 = __floats2half2_rn(f0.x, f0.y), h1 = __floats2half2_rn(f0.z, f0.w);
    __half2 h2 = __floats2half2_rn(f1.x, f1.y), h3 = __floats2half2_rn(f1.z, f1.w);
    *(uint4*)(g_wh + (size_t)i * 8) =
        make_uint4(*(uint*)&h0, *(uint*)&h1, *(uint*)&h2, *(uint*)&h3);
}
__global__ void prep_whhf(const float* __restrict__ Whh) {
    int idx = blockIdx.x * blockDim.x + threadIdx.x;
    if (idx >= 96 * 16 * 32) return;
    int lane = idx & 31, kt = (idx >> 5) & 15, nt = idx >> 9;
    int n = nt * 8 + (lane >> 2);
    int k0 = kt * 16 + (lane & 3) * 2;
    const float* s = Whh + (size_t)n * Hsz;
    __half2 lo = __floats2half2_rn(s[k0], s[k0 + 1]);
    __half2 hi = __floats2half2_rn(s[k0 + 8], s[k0 + 9]);
    g_Whf[idx] = make_uint2(*(uint*)&lo, *(uint*)&hi);
}
__global__ void prep_wof(const float* __restrict__ Wo, const float* __restrict__ Wg) {
    int idx = blockIdx.x * blockDim.x + threadIdx.x;
    if (idx >= 16 * 16 * 32) return;
    int lane = idx & 31, kt = (idx >> 5) & 15, nt = idx >> 9;
    int n = nt * 8 + (lane >> 2);
    int k0 = kt * 16 + (lane & 3) * 2;
    const float* s = (n < 64) ? (Wo + (size_t)n * Hsz) : (Wg + (size_t)(n - 64) * Hsz);
    __half2 lo = __floats2half2_rn(s[k0], s[k0 + 1]);
    __half2 hi = __floats2half2_rn(s[k0 + 8], s[k0 + 9]);
    g_Wof[idx] = make_uint2(*(uint*)&lo, *(uint*)&hi);
}

// ---------------- HMMA prepass GEMM v3 (unchanged from R15/16) --------------------------
__global__ void __launch_bounds__(256, 2) gemm_xi(const float* __restrict__ x,
                                                  const float* __restrict__ b_ih,
                                                  const float* __restrict__ bt) {
    extern __shared__ __align__(16) __half sh[];
    __half* Xs  = sh;                        // [128][XSTR]
    __half* WsA = sh + 128 * XSTR;
    __half* WsB = WsA + 128 * XSTR;

    const int tid = threadIdx.x, wid = tid >> 5, lane = tid & 31;
    const int rbase0 = blockIdx.x * 128;
    const int wm = wid & 1, wn = wid >> 1;

#pragma unroll
    for (int i = tid; i < 2048; i += 256) {
        int row = i >> 4, q = i & 15;
        cp_async16(smem_u32(WsA + row * XSTR + q * 8), g_wh + (size_t)i * 8);
    }
    CP_COMMIT();

#pragma unroll
    for (int i = tid; i < 2048; i += 256) {
        int row = i >> 4, q = i & 15;
        const float4* s = (const float4*)(x + (size_t)(rbase0 + row) * Isz + q * 8);
        float4 f0 = __ldg(s), f1 = __ldg(s + 1);
        __half2 h0 = __floats2half2_rn(f0.x, f0.y), h1 = __floats2half2_rn(f0.z, f0.w);
        __half2 h2 = __floats2half2_rn(f1.x, f1.y), h3 = __floats2half2_rn(f1.z, f1.w);
        *(uint4*)(Xs + row * XSTR + q * 8) =
            make_uint4(*(uint*)&h0, *(uint*)&h1, *(uint*)&h2, *(uint*)&h3);
    }

    for (int chunk = 0; chunk < 8; ++chunk) {
        __half* Wc = (chunk & 1) ? WsB : WsA;
        if (chunk < 7) {
            __half* Wd = (chunk & 1) ? WsA : WsB;
            const char* src = (const char*)(g_wh + (size_t)(chunk + 1) * 128 * Isz);
#pragma unroll
            for (int i = tid; i < 2048; i += 256) {
                int row = i >> 4, q = i & 15;
                cp_async16(smem_u32(Wd + row * XSTR + q * 8), src + (size_t)i * 16);
            }
            CP_COMMIT();
            CP_WAIT(1);
        } else {
            CP_WAIT(0);
        }
        __syncthreads();

        float acc[4][4][4];
#pragma unroll
        for (int mf = 0; mf < 4; ++mf)
#pragma unroll
            for (int nf = 0; nf < 4; ++nf)
#pragma unroll
                for (int q = 0; q < 4; ++q) acc[mf][nf][q] = 0.0f;

#pragma unroll
        for (int k = 0; k < 8; ++k) {
            uint a[4][4];
#pragma unroll
            for (int mf = 0; mf < 4; ++mf)
                ldm_x4(a[mf], Xs + (wm * 64 + mf * 16 + (lane & 15)) * XSTR
                                 + k * 16 + (lane >> 4) * 8);
            uint bf[4][2];
#pragma unroll
            for (int nf = 0; nf < 4; ++nf)
                ldm_x2(bf[nf], Wc + (wn * 32 + nf * 8 + (lane & 7)) * XSTR
                                  + k * 16 + ((lane >> 3) & 1) * 8);
#pragma unroll
            for (int mf = 0; mf < 4; ++mf)
#pragma unroll
                for (int nf = 0; nf < 4; ++nf)
                    mma16816(acc[mf][nf], a[mf], bf[nf]);
        }
        __syncthreads();

        const bool do_silu = (chunk >= 6);
#pragma unroll
        for (int nf = 0; nf < 4; ++nf) {
            int cl = wn * 32 + nf * 8 + (lane & 3) * 2;
            int cg = chunk * 128 + cl;
            float bias0, bias1;
            if (!do_silu) { bias0 = __ldg(b_ih + cg); bias1 = __ldg(b_ih + cg + 1); }
            else          { bias0 = __ldg(bt + cg - 768); bias1 = __ldg(bt + cg - 767); }
#pragma unroll
            for (int mf = 0; mf < 4; ++mf) {
#pragma unroll
                for (int h = 0; h < 2; ++h) {
                    int rl = wm * 64 + mf * 16 + (lane >> 2) + h * 8;
                    float v0 = acc[mf][nf][2 * h]     + bias0;
                    float v1 = acc[mf][nf][2 * h + 1] + bias1;
                    if (do_silu) { v0 *= sigmf(v0); v1 *= sigmf(v1); }
                    *(__half2*)(Wc + rl * XSTR + cl) = __floats2half2_rn(v0, v1);
                }
            }
        }
        __syncthreads();

#pragma unroll
        for (int ii = 0; ii < 8; ++ii) {
            int idx = tid + 256 * ii;
            int row = idx >> 4, q = idx & 15;
            uint4 v = *(uint4*)(Wc + row * XSTR + q * 8);
            *(uint4*)(g_xi + (size_t)(rbase0 + row) * 1024 + chunk * 128 + q * 8) = v;
        }
        __syncthreads();
    }
}

// ---------------- scan phase B: bias-seeded accumulators --------------------------------
__device__ __forceinline__ void phaseB(
    const __half* h16buf, float* hh, const uint2* wfa,
    int ntB, int ntC, int w, int lane,
    float2 bA, float2 bB, float2 bC)
{
    const __half* aB = h16buf + (lane & 15) * HSTR + (lane >> 4) * 8;
    float acc0[4] = {bA.x, bA.y, bA.x, bA.y};
    float acc1[4] = {bB.x, bB.y, bB.x, bB.y};
    float acc2[4] = {bC.x, bC.y, bC.x, bC.y};
    uint2 fb[2], fc[2];
    fb[0] = __ldg(&g_Whf[(ntB * 16 + 0) * 32 + lane]);
    fc[0] = __ldg(&g_Whf[(ntC * 16 + 0) * 32 + lane]);
    fb[1] = __ldg(&g_Whf[(ntB * 16 + 1) * 32 + lane]);
    fc[1] = __ldg(&g_Whf[(ntC * 16 + 1) * 32 + lane]);
#pragma unroll
    for (int kt = 0; kt < 16; ++kt) {
        const int s = kt & 1;
        uint a[4];
        ldm_x4(a, aB + kt * 16);
        uint2 cb = fb[s], cc2 = fc[s];
        if (kt + 2 < 16) {
            fb[s] = __ldg(&g_Whf[(ntB * 16 + kt + 2) * 32 + lane]);
            fc[s] = __ldg(&g_Whf[(ntC * 16 + kt + 2) * 32 + lane]);
        }
        mma16816(acc0, a, (uint*)&wfa[kt]);
        mma16816(acc1, a, (uint*)&cb);
        mma16816(acc2, a, (uint*)&cc2);
    }
    const int bb = lane >> 2, cc = w * 8 + 2 * (lane & 3);
    *(float2*)&hh[bb * 392 + cc]             = make_float2(acc0[0], acc0[1]);
    *(float2*)&hh[(bb + 8) * 392 + cc]       = make_float2(acc0[2], acc0[3]);
    *(float2*)&hh[bb * 392 + 128 + cc]       = make_float2(acc1[0], acc1[1]);
    *(float2*)&hh[(bb + 8) * 392 + 128 + cc] = make_float2(acc1[2], acc1[3]);
    *(float2*)&hh[bb * 392 + 256 + cc]       = make_float2(acc2[0], acc2[1]);
    *(float2*)&hh[(bb + 8) * 392 + 256 + cc] = make_float2(acc2[2], acc2[3]);
}

// ---------------- clustered GRU scan: merged BD, MUFU.TANH activations -------------------
__global__ void __launch_bounds__(STHR, 1) __cluster_dims__(2, 1, 1)
gru_scan(const float* __restrict__ h0, const float* __restrict__ b_hh,
         const float* __restrict__ bo, const float* __restrict__ bg,
         float* __restrict__ out)
{
    extern __shared__ __align__(16) char smraw[];
    const uint smb = smem_u32(smraw);

    const int tid  = threadIdx.x;
    const int w    = tid >> 5, lane = tid & 31;
    const int r    = blockIdx.x & 1;
    const int b0   = (blockIdx.x >> 1) * NBc;
    const uint rsmb = mapa_u32(smb, (uint)(r ^ 1));
    const uint mb   = smb + SM_MBAR;
    const uint rmb  = rsmb + SM_MBAR;

    const int jp  = tid & 63, j0 = 2 * jp;
    const int grp = tid >> 6;
    const int jg  = 128 * r + j0;

    const int ntA = 16 * r + w, ntB = 32 + 16 * r + w, ntC = 64 + 16 * r + w;

    const int wl = w & 7;
    const bool isG = (wl >= 4);
    const int ntD = isG ? (8 + 4 * r + (wl & 3)) : (4 * r + (wl & 3));
    const int colD = (isG ? 32 : 0) + (wl & 3) * 8 + 2 * (lane & 3);

    { // init h16[0] and h32 (own j-half)
        int b = tid >> 5, k0 = (tid & 31) * 8;
        const float4* p = (const float4*)(h0 + (size_t)(b0 + b) * Hsz + k0);
        float4 v0 = p[0], v1 = p[1];
        __half2 a0 = __floats2half2_rn(v0.x, v0.y), a1 = __floats2half2_rn(v0.z, v0.w);
        __half2 a2 = __floats2half2_rn(v1.x, v1.y), a3 = __floats2half2_rn(v1.z, v1.w);
        *(uint4*)(smraw + SM_H16(0) + (b * HSTR + k0) * 2) =
            make_uint4(*(uint*)&a0, *(uint*)&a1, *(uint*)&a2, *(uint*)&a3);
        int kq = (tid & 31) * 4;
        if (kq < 128) {
            float4 hv = *(const float4*)(h0 + (size_t)(b0 + b) * Hsz + 128 * r + kq);
            *(float4*)(smraw + SM_H32 + (b * 128 + kq) * 4) = hv;
        }
    }
    if (tid == 0) mbar_init(mb, 1);

    // register-cached invariant fragments
    uint2 wfa[16];
#pragma unroll
    for (int kt = 0; kt < 16; ++kt)
        wfa[kt] = __ldg(&g_Whf[(ntA * 16 + kt) * 32 + lane]);
    uint2 wofr[8];
    if (w < 8) {
#pragma unroll
        for (int ki = 0; ki < 8; ++ki)
            wofr[ki] = __ldg(&g_Wof[(ntD * 16 + ki) * 32 + lane]);
    }
    // phase-B bias seeds (per-lane columns of b_hh)
    const float2 bA = *(const float2*)(b_hh + ntA * 8 + 2 * (lane & 3));
    const float2 bB = *(const float2*)(b_hh + ntB * 8 + 2 * (lane & 3));
    const float2 bC = *(const float2*)(b_hh + ntC * 8 + 2 * (lane & 3));

    { // prologue: stage xi(0)
#pragma unroll
        for (int ii = 0; ii < 2; ++ii) {
            int i = tid + 512 * ii;
            int pair = i >> 4, q = i & 15;
            int b = pair >> 2, seg = pair & 3;
            const uint4* src = (const uint4*)(g_xi +
                ((size_t)(b0 + b) * Tsz) * 1024 + seg * 256 + 128 * r) + q;
            *((uint4*)((__half*)(smraw + SM_XI) + b * 512 + seg * 128) + q) = __ldg(src);
        }
    }

    const float boT = __ldg(bo + 32 * r + (tid & 31));
    const float bgT = __ldg(bg + 32 * r + (tid & 31));
    float oacc = 0.0f;

    __syncthreads();
    CLUSTER_SYNC();   // mbarrier init + h16[0] visible cluster-wide

    // prologue: B(0) -> hh
    phaseB((const __half*)(smraw + SM_H16(0)), (float*)(smraw + SM_HH),
           wfa, ntB, ntC, w, lane, bA, bB, bC);
    __syncthreads();  // hh(0) ready

    for (int t = 0; t < Tsz; ++t) {
        const int p = t & 1;
        __half* h16n  = (__half*)(smraw + SM_H16(p ^ 1));
        __half* v16n  = (__half*)(smraw + SM_V16(p ^ 1));
        __half* xi_s  = (__half*)(smraw + SM_XI);
        float*  hh    = (float*)(smraw + SM_HH);
        float*  h32   = (float*)(smraw + SM_H32);
        float*  redP  = (float*)(smraw + SM_REDP);

        if (tid == 0) mbar_expect_tx(mb, TX_BYTES);

        // ---- Phase C: gates + update (MUFU.TANH activations, biases pre-folded) ----
#pragma unroll
        for (int q = 0; q < 2; ++q) {
            const int b = grp + 8 * q;
            const __half2* xp = (const __half2*)(xi_s + b * 512 + j0);
            float2 xr = __half22float2(xp[0]);
            float2 xz = __half22float2(xp[64]);
            float2 xn = __half22float2(xp[128]);
            float2 xt = __half22float2(xp[192]);
            const float* hhb = hh + b * 392;
            float2 hr = *(const float2*)(hhb + j0);
            float2 hz = *(const float2*)(hhb + 128 + j0);
            float2 hn = *(const float2*)(hhb + 256 + j0);
            float2 hp = *(const float2*)(h32 + b * 128 + j0);

            float r0 = sig_ap(xr.x + hr.x);
            float r1 = sig_ap(xr.y + hr.y);
            float z0 = sig_ap(xz.x + hz.x);
            float z1 = sig_ap(xz.y + hz.y);
            float n0 = tanh_ap(xn.x + r0 * hn.x);
            float n1 = tanh_ap(xn.y + r1 * hn.y);
            float h0n = n0 + z0 * (hp.x - n0);
            float h1n = n1 + z1 * (hp.y - n1);
            *(float2*)(h32 + b * 128 + j0) = make_float2(h0n, h1n);

            __half2 hh2 = __floats2half2_rn(h0n, h1n);
            __half2 vv2 = __floats2half2_rn(h0n + xt.x, h1n + xt.y);
            const uint off_h = (uint)SM_H16(p ^ 1) + (b * HSTR + jg) * 2;
            const uint off_v = (uint)SM_V16(p ^ 1) + (b * HSTR + jg) * 2;
            *(__half2*)(smraw + off_h) = hh2;
            *(__half2*)(smraw + off_v) = vv2;
            st_async_u32(rsmb + off_h, *(uint*)&hh2, rmb);
            st_async_u32(rsmb + off_v, *(uint*)&vv2, rmb);
        }
        __syncthreads();               // local C writes + hh/xi consumption complete
        mbar_wait(mb, (uint)(t & 1));  // peer's st.async halves arrived

        // ---- Merged BD: D(t) (warps 0-7) / xi(t+1) staging (warps 8-15), then B(t+1) ----
        if (w < 8) {
            const __half* aD = (isG ? h16n : v16n) + (lane & 15) * HSTR + (lane >> 4) * 8;
            float acc[4] = {0.f, 0.f, 0.f, 0.f};
#pragma unroll
            for (int ki = 0; ki < 8; ++ki) {
                uint a[4];
                ldm_x4(a, aD + ki * 16);
                mma16816(acc, a, (uint*)&wofr[ki]);
            }
#pragma unroll
            for (int ki = 8; ki < 16; ++ki) {
                uint a[4];
                ldm_x4(a, aD + ki * 16);
                uint2 wf = __ldg(&g_Wof[(ntD * 16 + ki) * 32 + lane]);  // L1-warm
                mma16816(acc, a, (uint*)&wf);
            }
            const int bb = lane >> 2;
            *(float2*)&redP[bb * 64 + colD]       = make_float2(acc[0], acc[1]);
            *(float2*)&redP[(bb + 8) * 64 + colD] = make_float2(acc[2], acc[3]);
        } else if (t + 1 < Tsz) {
            const int tt = tid & 255;
#pragma unroll
            for (int ii = 0; ii < 4; ++ii) {
                int i = tt + 256 * ii;
                int pair = i >> 4, q = i & 15;
                int b = pair >> 2, seg = pair & 3;
                const uint4* src = (const uint4*)(g_xi +
                    ((size_t)(b0 + b) * Tsz + t + 1) * 1024 + seg * 256 + 128 * r) + q;
                *((uint4*)(xi_s + b * 512 + seg * 128) + q) = __ldg(src);
            }
        }
        // B(t+1): reads h16n (state after C(t)); writes hh for C(t+1)
        if (t + 1 < Tsz)
            phaseB(h16n, hh, wfa, ntB, ntC, w, lane, bA, bB, bC);
        __syncthreads();  // redP + hh(t+1) + xi(t+1) ready

        { // finalize(t)
            const int b = tid >> 5, c = tid & 31;
            float pr = redP[b * 64 + c] + boT;
            float gt = redP[b * 64 + 32 + c] + bgT;
            oacc += pr * sig_ap(gt);
        }
    }

    { // output: CTA r writes cols [32r, 32r+32)
        const int b = tid >> 5, c = tid & 31;
        out[(size_t)(b0 + b) * Osz + 32 * r + c] = oacc * (1.0f / (float)Tsz);
    }
    CLUSTER_SYNC();   // keep smem alive until peer fully drained
}

// ---------------- launch -----------------------------------------------------------------
extern "C" void kernel_launch(void* const* d_in, const int* in_sizes, int n_in,
                              void* d_out, int out_size) {
    const float* x    = (const float*)d_in[0];
    const float* h0   = (const float*)d_in[1];
    const float* W_ih = (const float*)d_in[2];
    const float* b_ih = (const float*)d_in[3];
    const float* W_hh = (const float*)d_in[4];
    const float* b_hh = (const float*)d_in[5];
    const float* Wt   = (const float*)d_in[6];
    const float* bt   = (const float*)d_in[7];
    const float* Wo   = (const float*)d_in[8];
    const float* bo   = (const float*)d_in[9];
    const float* Wg   = (const float*)d_in[10];
    const float* bg   = (const float*)d_in[11];
    float* out = (float*)d_out;

    const int GEMM_SMEM = 3 * 128 * XSTR * 2;   // 104448
    cudaFuncSetAttribute(gemm_xi, cudaFuncAttributeMaxDynamicSharedMemorySize, GEMM_SMEM);
    cudaFuncSetAttribute(gru_scan, cudaFuncAttributeMaxDynamicSharedMemorySize, SM_TOTAL);

    pack_wh<<<(1024 * Isz / 8 + 255) / 256, 256>>>(W_ih, Wt);
    prep_whhf<<<(96 * 16 * 32 + 255) / 256, 256>>>(W_hh);
    prep_wof<<<(16 * 16 * 32 + 255) / 256, 256>>>(Wo, Wg);
    gemm_xi<<<(Bsz * Tsz) / 128, 256, GEMM_SMEM>>>(x, b_ih, bt);
    gru_scan<<<NCTA, STHR, SM_TOTAL>>>(h0, b_hh, bo, bg, out);
}